// round 1
// baseline (speedup 1.0000x reference)
#include <cuda_runtime.h>
#include <math.h>

#define PI_F    3.14159265358979f
#define INVPI_F 0.3183098861837907f
#define EPS_F   1e-12f
#define NPTS    1000

__device__ float g_scal[4];  // zs_max, L_max, zs_crit, L_crit

struct Coefs {
    float F0, F1, F2, F3, F4, FL;   // f(z) = P4(z) + FL*z^4*ln z
    float Q0, Q1, Q2, Q3, Q4;       // df = (Q4(z) + 4f)/z
    float c0, c1, c2, c3;           // bp(z), B = bp^2
    float d1, d2, d3;               // bp'(z)
};

// ---- fast approx MUFU ops (inline PTX) ----
static __device__ __forceinline__ float frcp(float x){ float r; asm("rcp.approx.f32 %0, %1;"   : "=f"(r) : "f"(x)); return r; }
static __device__ __forceinline__ float frsq(float x){ float r; asm("rsqrt.approx.f32 %0, %1;" : "=f"(r) : "f"(x)); return r; }
static __device__ __forceinline__ float fsqt(float x){ float r; asm("sqrt.approx.f32 %0, %1;"  : "=f"(r) : "f"(x)); return r; }
static __device__ __forceinline__ float flg (float x){ float r; asm("lg2.approx.f32 %0, %1;"   : "=f"(r) : "f"(x)); return r * 0.693147180559945f; }

static __device__ __forceinline__ void make_coefs(float a0, float a1, float b0, float b1, Coefs& C)
{
    float w1 = 2.f*a0;
    float w2 = fmaf(a0, a0, 2.f*a1);
    float w3 = 2.f*a0*a1;
    float w4 = a1*a1;
    C.F0 = 1.f;
    C.F1 = (4.f/3.f)*w1;
    C.F2 = 2.f*w2;
    C.F3 = 4.f*w3;
    C.F4 = -(C.F0 + C.F1 + C.F2 + C.F3);   // ensures f(1)=0 (analytic identity)
    C.FL = -4.f*w4;
    C.Q0 = -4.f;
    C.Q1 = -4.f*w1;
    C.Q2 = -4.f*w2;
    C.Q3 = -4.f*w3;
    C.Q4 = -4.f*w4;
    C.c0 = 1.f; C.c1 = b0; C.c2 = b1;
    C.c3 = ((a0 + a1) - b0) - b1;
    C.d1 = C.c1; C.d2 = 2.f*C.c2; C.d3 = 3.f*C.c3;
}

static __device__ __forceinline__ void eval_fdf(const Coefs& C, float z, float& f, float& df)
{
    float z2 = z*z, z4 = z2*z2;
    float p = fmaf(fmaf(fmaf(fmaf(C.F4, z, C.F3), z, C.F2), z, C.F1), z, C.F0);
    f = fmaf(C.FL*z4, flg(z), p);
    float q = fmaf(fmaf(fmaf(fmaf(C.Q4, z, C.Q3), z, C.Q2), z, C.Q1), z, C.Q0);
    df = fmaf(4.f, f, q) * frcp(z);
}

// Fused integrands of integrate_L and integrate_dL at one quadrature point.
static __device__ __forceinline__ void ldl_point(const Coefs& C, float zs, float inv_fs,
                                                 float K1, float zsif,
                                                 float y, float omy2, float r4,
                                                 float& iL, float& idL)
{
    float z  = zs * omy2;
    float z2 = z*z, z4 = z2*z2;
    float p  = fmaf(fmaf(fmaf(fmaf(C.F4, z, C.F3), z, C.F2), z, C.F1), z, C.F0);
    float f  = fmaf(C.FL*z4, flg(z), p);
    float q  = fmaf(fmaf(fmaf(fmaf(C.Q4, z, C.Q3), z, C.Q2), z, C.Q1), z, C.Q0);
    float df = fmaf(4.f, f, q) * frcp(z);
    float bp  = fmaf(fmaf(fmaf(C.c3, z, C.c2), z, C.c1), z, C.c0);
    float dbp = fmaf(fmaf(C.d3, z, C.d2), z, C.d1);
    float B   = bp*bp;
    float dB  = 2.f*dbp*bp;
    float Dd  = (1.f - z)*(1.f + z)*fmaf(z, z, 1.f);
    float invD = frcp(Dd);
    float g   = B*invD;
    float sg  = fsqt(g);
    float fr  = f * inv_fs;
    float r4fr = r4 * fr;
    float m   = fmaxf(r4fr - 1.f, EPS_F);
    float rm  = frsq(m);
    iL = sg * rm * y;
    float zdgg = fmaf(z*dB, frcp(B), 4.f*z4*invD);       // z*dg/g
    float A1 = r4fr * ((K1 + 2.f) + zdgg);
    float A2 = (r4*omy2) * df * zsif;                    // zs^4/z^3 * df/fs
    float brk = ((A1 - A2) - 2.f) - zdgg;
    idL = brk * (2.f*y) * sg * (rm*rm*rm);               // sqrt(1-z/zs)=y exactly
}

// integrate_V connected-piece integrand.
static __device__ __forceinline__ float vc_point(const Coefs& C, float zs, float fs,
                                                 float y, float omy2, float r4)
{
    float z  = zs * omy2;
    float z2 = z*z, z4 = z2*z2;
    float p  = fmaf(fmaf(fmaf(fmaf(C.F4, z, C.F3), z, C.F2), z, C.F1), z, C.F0);
    float f  = fmaf(C.FL*z4, flg(z), p);
    float bp = fmaf(fmaf(fmaf(C.c3, z, C.c2), z, C.c1), z, C.c0);
    float B  = bp*bp;
    float Dd = (1.f - z)*(1.f + z)*fmaf(z, z, 1.f);
    float g  = B * frcp(Dd);
    float fg = fmaxf(f*g, EPS_F);
    float w  = omy2*omy2;
    float tt = fmaxf(1.f - (w*w)*fs*frcp(f), EPS_F);     // 1 - w^2/(f/fs)
    (void)r4;
    return fsqt(fg) * frcp(w) * (frsq(tt) - 1.f) * y;
}

// integrate_V disconnected-piece integrand (own grid).
static __device__ __forceinline__ float vd_point(const Coefs& C, float zs, float y2)
{
    float z  = 1.f - (1.f - zs)*y2;
    float z2 = z*z, z4 = z2*z2;
    float p  = fmaf(fmaf(fmaf(fmaf(C.F4, z, C.F3), z, C.F2), z, C.F1), z, C.F0);
    float f  = fmaf(C.FL*z4, flg(z), p);
    float bp = fmaf(fmaf(fmaf(C.c3, z, C.c2), z, C.c1), z, C.c0);
    float B  = bp*bp;
    float Dd = (1.f - z)*(1.f + z)*fmaf(z, z, 1.f);
    float g  = B * frcp(Dd);
    float fg = fmaxf(f*g, EPS_F);
    return fsqt(fg) * frcp(z2);
}

// ---------------------------------------------------------------------------
// Phase A: one block, 1024 threads. Bisections for zs_max / zs_crit, L_max,
// L_crit. Thread t owns quadrature point t (t < 1000).
// ---------------------------------------------------------------------------
static __device__ float breduce1024(float v)
{
    __shared__ float buf[32];
    #pragma unroll
    for (int o = 16; o; o >>= 1) v += __shfl_xor_sync(0xffffffffu, v, o);
    int w = threadIdx.x >> 5, l = threadIdx.x & 31;
    if (l == 0) buf[w] = v;
    __syncthreads();
    if (w == 0) {
        v = buf[l];
        #pragma unroll
        for (int o = 16; o; o >>= 1) v += __shfl_xor_sync(0xffffffffu, v, o);
        if (l == 0) buf[0] = v;
    }
    __syncthreads();
    v = buf[0];
    __syncthreads();   // protect buf for next call
    return v;
}

static __device__ void calc_LdL_block(const Coefs& C, float zs, bool act,
                                      float y, float omy2, float r4, float W,
                                      float& Lv, float& dLv)
{
    float fs, dfs; eval_fdf(C, zs, fs, dfs);
    float inv_fs = frcp(fs);
    float K1 = zs * dfs * inv_fs;
    float zsif = zs * inv_fs;
    float iL = 0.f, idL = 0.f;
    if (act) ldl_point(C, zs, inv_fs, K1, zsif, y, omy2, r4, iL, idL);
    float sL = breduce1024(act ? W * iL : 0.f);
    float sD = breduce1024(act ? W * idL : 0.f);
    Lv  = 4.f * zs * sL * INVPI_F;
    dLv = sD * INVPI_F;
}

static __device__ float calc_V_block(const Coefs& C, float coef, float zs, bool act,
                                     float y, float omy2, float r4, float W,
                                     float yd, float W2)
{
    float fs, dfs; eval_fdf(C, zs, fs, dfs);
    float ic = 0.f, idd = 0.f;
    if (act) {
        ic  = W  * vc_point(C, zs, fs, y, omy2, r4);
        idd = W2 * vd_point(C, zs, yd);
    }
    float sC = breduce1024(ic);
    float sD = breduce1024(idd) + 0.0005f;   // prepended "1" sample: 0.5*1*0.001
    float Vc = coef * PI_F * 4.f * sC / zs;
    float Vd = coef * PI_F * 2.f * (1.f - zs) * sD;
    return Vc - Vd;
}

__global__ void __launch_bounds__(1024) k_precompute(const float* a, const float* b, const float* lc)
{
    const int tid = threadIdx.x;
    const bool act = tid < NPTS;
    Coefs C; make_coefs(a[0], a[1], b[0], b[1], C);
    const float h  = 0.998f / 999.f;
    const float h2 = 0.999f / 999.f;
    float y = 0.5f, omy2 = 0.75f, r4 = 1.f, W = 0.f, yd = 0.5f, W2 = 0.f;
    if (act) {
        y    = 0.001f + h * (float)tid;
        omy2 = (1.f - y)*(1.f + y);
        float t2 = omy2*omy2;
        r4 = 1.0f / (t2*t2);
        W = h;
        if      (tid == 0)   W = 0.5f*h + 0.001f + 0.5f*(1.0e-6f)/h; // folds _extend extrapolation
        else if (tid == 1)   W = h - 0.5f*(1.0e-6f)/h;
        else if (tid == 999) W = 0.5f*h + 0.5f*(1.f - y);
        yd = 0.001f + h2 * (float)tid;
        W2 = (tid == 0) ? (0.0005f + 0.5f*h2) : ((tid == 999) ? 0.5f*h2 : h2);
    }
    float coef = expf(lc[0]);

    // bisect zs_max on integrate_dL
    float lo = 0.001f, hi = 0.999f;
    for (int i = 0; i < 30; ++i) {
        float mid = 0.5f*(lo + hi);
        float Lv, dLv;
        calc_LdL_block(C, mid, act, y, omy2, r4, W, Lv, dLv);
        if (dLv < 0.f) hi = mid; else lo = mid;
    }
    float zs_max = 0.5f*(lo + hi);
    float L_max, dum;
    calc_LdL_block(C, zs_max, act, y, omy2, r4, W, L_max, dum);

    // bisect zs_crit on -integrate_V over (0.001, zs_max)
    lo = 0.001f; hi = zs_max;
    for (int i = 0; i < 30; ++i) {
        float mid = 0.5f*(lo + hi);
        float V = calc_V_block(C, coef, mid, act, y, omy2, r4, W, yd, W2);
        if (-V < 0.f) hi = mid; else lo = mid;
    }
    float zs_crit = 0.5f*(lo + hi);
    float L_crit;
    calc_LdL_block(C, zs_crit, act, y, omy2, r4, W, L_crit, dum);

    if (tid == 0) {
        g_scal[0] = zs_max; g_scal[1] = L_max;
        g_scal[2] = zs_crit; g_scal[3] = L_crit;
    }
}

// ---------------------------------------------------------------------------
// Phase B: one warp per batch element. Newton (<=25 steps, exact early exit
// via fixed-point / 2-cycle detection) + final V.
// ---------------------------------------------------------------------------
__global__ void __launch_bounds__(256) k_solve(const float* __restrict__ Ls,
                                               const float* __restrict__ a,
                                               const float* __restrict__ b,
                                               const float* __restrict__ lc,
                                               float* __restrict__ out, int B)
{
    __shared__ float4 tab[NPTS];    // y, (1-y)(1+y), r4, trapz weight
    const float h  = 0.998f / 999.f;
    const float h2 = 0.999f / 999.f;
    for (int k = threadIdx.x; k < NPTS; k += blockDim.x) {
        float y = 0.001f + h * (float)k;
        float omy2 = (1.f - y)*(1.f + y);
        float t2 = omy2*omy2;
        float r4 = 1.0f / (t2*t2);
        float W = h;
        if      (k == 0)   W = 0.5f*h + 0.001f + 0.5f*(1.0e-6f)/h;
        else if (k == 1)   W = h - 0.5f*(1.0e-6f)/h;
        else if (k == 999) W = 0.5f*h + 0.5f*(1.f - y);
        tab[k] = make_float4(y, omy2, r4, W);
    }
    __syncthreads();

    int gw = (blockIdx.x * blockDim.x + threadIdx.x) >> 5;
    if (gw >= B) return;
    int lane = threadIdx.x & 31;

    Coefs C; make_coefs(a[0], a[1], b[0], b[1], C);
    float zs_max = g_scal[0], L_max = g_scal[1], L_crit = g_scal[3];
    float coef = expf(lc[0]);

    float Lq = Ls[gw];
    bool valid = Lq < L_crit;
    float L_eff = valid ? Lq : 0.5f * L_crit;
    float zs = fminf(fmaxf(L_eff / L_max * zs_max, 1e-4f), 0.9995f);

    float zpp = -1.f;   // zs two steps ago
    for (int it = 0; it < 25; ++it) {
        float fs, dfs; eval_fdf(C, zs, fs, dfs);
        float inv_fs = frcp(fs);
        float K1 = zs * dfs * inv_fs;
        float zsif = zs * inv_fs;
        float sL = 0.f, sD = 0.f;
        for (int k = lane; k < NPTS; k += 32) {
            float4 t = tab[k];
            float iL, idL;
            ldl_point(C, zs, inv_fs, K1, zsif, t.x, t.y, t.z, iL, idL);
            sL = fmaf(t.w, iL, sL);
            sD = fmaf(t.w, idL, sD);
        }
        #pragma unroll
        for (int o = 16; o; o >>= 1) {
            sL += __shfl_xor_sync(0xffffffffu, sL, o);
            sD += __shfl_xor_sync(0xffffffffu, sD, o);
        }
        float Lv  = 4.f * zs * sL * INVPI_F;
        float dLv = sD * INVPI_F;
        float zn = zs - (Lv - L_eff) / dLv;
        zn = fminf(fmaxf(zn, 1e-4f), 0.9995f);
        if (zn == zs) break;                        // exact fixed point
        if (zn == zpp) {                            // exact 2-cycle: parity decides final
            int rem = 24 - it;                      // steps remaining after this one
            if (!(rem & 1)) zs = zn;                // even: lands on zn; odd: stays on zs
            break;
        }
        zpp = zs; zs = zn;
    }

    // Final V at the Newton root.
    float fs, dfs; eval_fdf(C, zs, fs, dfs);
    float sC = 0.f, sD2 = 0.f;
    for (int k = lane; k < NPTS; k += 32) {
        float4 t = tab[k];
        sC = fmaf(t.w, vc_point(C, zs, fs, t.x, t.y, t.z), sC);
        float yq = 0.001f + h2 * (float)k;
        float W2 = (k == 0) ? (0.0005f + 0.5f*h2) : ((k == 999) ? 0.5f*h2 : h2);
        sD2 = fmaf(W2, vd_point(C, zs, yq), sD2);
    }
    #pragma unroll
    for (int o = 16; o; o >>= 1) {
        sC  += __shfl_xor_sync(0xffffffffu, sC,  o);
        sD2 += __shfl_xor_sync(0xffffffffu, sD2, o);
    }
    sD2 += 0.0005f;
    float Vc = coef * PI_F * 4.f * sC / zs;
    float Vd = coef * PI_F * 2.f * (1.f - zs) * sD2;
    float V = Vc - Vd;

    if (lane == 0) out[gw] = valid ? V : 0.f;
}

extern "C" void kernel_launch(void* const* d_in, const int* in_sizes, int n_in,
                              void* d_out, int out_size)
{
    const float* Ls = (const float*)d_in[0];
    const float* a  = (const float*)d_in[1];
    const float* b  = (const float*)d_in[2];
    const float* lc = (const float*)d_in[3];
    float* out = (float*)d_out;
    int B = in_sizes[0];

    k_precompute<<<1, 1024>>>(a, b, lc);

    int threads = 256;
    int blocks = (B * 32 + threads - 1) / threads;
    if (blocks > 0)
        k_solve<<<blocks, threads>>>(Ls, a, b, lc, out, B);
}

// round 2
// speedup vs baseline: 4.9877x; 4.9877x over previous
#include <cuda_runtime.h>
#include <math.h>

#define PI_F     3.14159265358979f
#define INVPI_F  0.3183098861837907f
#define EPS_F    1e-12f
#define NPTS     1000
#define TABN     4096
#define ZLO      1e-4f
#define LN2_F    0.69314718055994531f

__device__ float g_scal[4];      // zs_max, L_max, zs_crit, L_crit
__device__ float g_Ltab[TABN];   // L(zs) on uniform grid [ZLO, zs_max]

struct Coefs {
    float F1, F2, F3, F4, FLln2;   // f(z) = 1 + F1 z + ... + F4 z^4 + (FLln2*z^4)*lg2(z)
    float Q1, Q2, Q3, Q4;          // q(z) = -4 + Q1 z + ...; df = (4f+q)/z
    float c1, c2, c3;              // bp(z) = 1 + c1 z + c2 z^2 + c3 z^3; B = bp^2
    float d2, d3;                  // bp'(z) = c1 + d2 z + d3 z^2
};

static __device__ __forceinline__ float frcp(float x){ float r; asm("rcp.approx.f32 %0,%1;"   : "=f"(r) : "f"(x)); return r; }
static __device__ __forceinline__ float frsq(float x){ float r; asm("rsqrt.approx.f32 %0,%1;" : "=f"(r) : "f"(x)); return r; }
static __device__ __forceinline__ float fsqt(float x){ float r; asm("sqrt.approx.f32 %0,%1;"  : "=f"(r) : "f"(x)); return r; }
static __device__ __forceinline__ float flg2(float x){ float r; asm("lg2.approx.f32 %0,%1;"   : "=f"(r) : "f"(x)); return r; }

static __device__ __forceinline__ void make_coefs(float a0, float a1, float b0, float b1, Coefs& C)
{
    float w1 = 2.f*a0;
    float w2 = fmaf(a0, a0, 2.f*a1);
    float w3 = 2.f*a0*a1;
    float w4 = a1*a1;
    C.F1 = (4.f/3.f)*w1;
    C.F2 = 2.f*w2;
    C.F3 = 4.f*w3;
    C.F4 = -(1.f + C.F1 + C.F2 + C.F3);   // f(1)=0 identity
    float FL = -4.f*w4;
    C.FLln2 = FL * LN2_F;                 // fold ln2 so we can use raw lg2.approx
    C.Q1 = -4.f*w1; C.Q2 = -4.f*w2; C.Q3 = -4.f*w3; C.Q4 = FL;
    C.c1 = b0; C.c2 = b1;
    C.c3 = ((a0 + a1) - b0) - b1;
    C.d2 = 2.f*C.c2; C.d3 = 3.f*C.c3;
}

static __device__ __forceinline__ float evalf(const Coefs& C, float z, float& z2, float& z4)
{
    z2 = z*z; z4 = z2*z2;
    float p = fmaf(fmaf(fmaf(fmaf(C.F4, z, C.F3), z, C.F2), z, C.F1), z, 1.f);
    return fmaf(C.FLln2*z4, flg2(z), p);
}

static __device__ __forceinline__ void eval_fdf(const Coefs& C, float z, float& f, float& df)
{
    float z2, z4; f = evalf(C, z, z2, z4);
    float q = fmaf(fmaf(fmaf(fmaf(C.Q4, z, C.Q3), z, C.Q2), z, C.Q1), z, -4.f);
    df = fmaf(4.f, f, q) * frcp(z);
}

// Fused L + dL integrand at one quadrature point. idL omits factor 2 (folded
// into 2/pi at the end).
static __device__ __forceinline__ void ldl_point(const Coefs& C, float zs, float inv_fs, float K12,
                                                 float y, float omy2, float r4,
                                                 float& iL, float& idL)
{
    float z = zs*omy2;
    float z2, z4; float f = evalf(C, z, z2, z4);
    float q = fmaf(fmaf(fmaf(fmaf(C.Q4, z, C.Q3), z, C.Q2), z, C.Q1), z, -4.f);
    float t4 = fmaf(4.f, f, q);                       // 4f + q = z*df
    float fr = f*inv_fs;
    float r4fr = r4*fr;
    float m = fmaxf(r4fr - 1.f, EPS_F);
    float rm = frsq(m);
    float bp  = fmaf(fmaf(fmaf(C.c3, z, C.c2), z, C.c1), z, 1.f);
    float dbp = fmaf(fmaf(C.d3, z, C.d2), z, C.c1);
    float Dd = (1.f - z2)*(1.f + z2);                 // 1 - z^4
    float rsq = frsq(Dd);
    float invD = rsq*rsq;
    float sg = bp*rsq;                                // sqrt(g) = bp/sqrt(D)
    iL = sg*rm*y;
    float zdgg = fmaf(2.f*z*dbp, frcp(bp), 4.f*(z4*invD));   // z*dg/g
    float A1 = r4fr*(K12 + zdgg);
    float A2 = t4*(r4*inv_fs);                        // zs^4/z^3 * df/fs
    float brk = (A1 - A2) - (2.f + zdgg);
    idL = brk*iL*(rm*rm);                             // = brk * sg * y * rm^3
}

// L-only integrand (table build, L_max / L_crit evaluations)
static __device__ __forceinline__ float L_point(const Coefs& C, float zs, float inv_fs,
                                                float y, float omy2, float r4)
{
    float z = zs*omy2;
    float z2, z4; float f = evalf(C, z, z2, z4);
    float m = fmaxf(r4*(f*inv_fs) - 1.f, EPS_F);
    float bp = fmaf(fmaf(fmaf(C.c3, z, C.c2), z, C.c1), z, 1.f);
    float Dd = (1.f - z2)*(1.f + z2);
    float sg = bp*frsq(Dd);
    return sg*frsq(m)*y;
}

// V connected integrand
static __device__ __forceinline__ float vc_point(const Coefs& C, float zs, float fs,
                                                 float y, float omy2)
{
    float z = zs*omy2;
    float z2, z4; float f = evalf(C, z, z2, z4);
    float bp = fmaf(fmaf(fmaf(C.c3, z, C.c2), z, C.c1), z, 1.f);
    float Dd = (1.f - z2)*(1.f + z2);
    float rsq = frsq(Dd);
    float invD = rsq*rsq;
    float fg = fmaxf(f*(bp*bp)*invD, EPS_F);
    float sfg = fsqt(fg);
    float w = omy2*omy2;
    float tt = fmaxf(fmaf(-(w*w)*fs, frcp(f), 1.f), EPS_F);  // 1 - w^2*fs/f
    return sfg*frcp(w)*(frsq(tt) - 1.f)*y;
}

// V disconnected integrand (own grid y2 on [0.001, 1.0])
static __device__ __forceinline__ float vd_point(const Coefs& C, float zs, float y2)
{
    float z = fmaf(zs - 1.f, y2, 1.f);                // 1 - (1-zs)*y2
    float z2, z4; float f = evalf(C, z, z2, z4);
    float bp = fmaf(fmaf(fmaf(C.c3, z, C.c2), z, C.c1), z, 1.f);
    float Dd = (1.f - z2)*(1.f + z2);
    float rsq = frsq(Dd);
    float invD = rsq*rsq;
    float fg = fmaxf(f*(bp*bp)*invD, EPS_F);
    float rz = frcp(z);
    return fsqt(fg)*(rz*rz);
}

// Shared quadrature table: y, (1-y)(1+y), r4 = (1-y^2)^-4, trapz weight
// (endpoint weights fold the _extend extrapolation in closed form).
static __device__ void build_tab(float4* tab)
{
    const float h = 0.998f/999.f;
    for (int k = threadIdx.x; k < NPTS; k += blockDim.x) {
        float y = 0.001f + h*(float)k;
        float omy2 = (1.f - y)*(1.f + y);
        float t2 = omy2*omy2;
        float r4 = 1.f/(t2*t2);
        float W = h;
        if      (k == 0)   W = 0.5f*h + 0.001f + 0.5f*(1.0e-6f)/h;
        else if (k == 1)   W = h - 0.5f*(1.0e-6f)/h;
        else if (k == 999) W = 0.5f*h + 0.5f*(1.f - y);
        tab[k] = make_float4(y, omy2, r4, W);
    }
}

// ---------------------------------------------------------------------------
// Phase A: bisections. 1 block x 1024 threads, thread t owns point t. Lean
// single-value block reduction (2 syncthreads, result broadcast to all).
// ---------------------------------------------------------------------------
static __device__ __forceinline__ float bsum(float v)
{
    __shared__ float buf[32];
    #pragma unroll
    for (int o = 16; o; o >>= 1) v += __shfl_xor_sync(0xffffffffu, v, o);
    int w = threadIdx.x >> 5, l = threadIdx.x & 31;
    if (l == 0) buf[w] = v;
    __syncthreads();
    float t = buf[l];
    #pragma unroll
    for (int o = 16; o; o >>= 1) t += __shfl_xor_sync(0xffffffffu, t, o);
    __syncthreads();
    return t;
}

__global__ void __launch_bounds__(1024) k_precompute(const float* a, const float* b, const float* lc)
{
    const int tid = threadIdx.x;
    const bool act = tid < NPTS;
    Coefs C; make_coefs(a[0], a[1], b[0], b[1], C);
    const float h  = 0.998f/999.f;
    const float h2 = 0.999f/999.f;
    float y = 0.5f, omy2 = 0.75f, r4 = 1.f, W = 0.f, yd = 0.5f, W2 = 0.f;
    if (act) {
        y = 0.001f + h*(float)tid;
        omy2 = (1.f - y)*(1.f + y);
        float t2 = omy2*omy2;
        r4 = 1.f/(t2*t2);
        W = h;
        if      (tid == 0)   W = 0.5f*h + 0.001f + 0.5f*(1.0e-6f)/h;
        else if (tid == 1)   W = h - 0.5f*(1.0e-6f)/h;
        else if (tid == 999) W = 0.5f*h + 0.5f*(1.f - y);
        yd = 0.001f + h2*(float)tid;
        W2 = (tid == 0) ? (0.0005f + 0.5f*h2) : ((tid == 999) ? 0.5f*h2 : h2);
    }
    float coef = expf(lc[0]);

    // bisect zs_max on sign(dL)
    float lo = 0.001f, hi = 0.999f;
    for (int i = 0; i < 30; ++i) {
        float mid = 0.5f*(lo + hi);
        float fs, dfs; eval_fdf(C, mid, fs, dfs);
        float inv_fs = frcp(fs);
        float K12 = fmaf(mid*dfs, inv_fs, 2.f);
        float iL = 0.f, idL = 0.f;
        if (act) ldl_point(C, mid, inv_fs, K12, y, omy2, r4, iL, idL);
        float sD = bsum(act ? W*idL : 0.f);
        if (sD < 0.f) hi = mid; else lo = mid;
    }
    float zs_max = 0.5f*(lo + hi);

    float L_max;
    {
        float fs, dfs; eval_fdf(C, zs_max, fs, dfs);
        float inv_fs = frcp(fs);
        float s = bsum(act ? W*L_point(C, zs_max, inv_fs, y, omy2, r4) : 0.f);
        L_max = 4.f*zs_max*s*INVPI_F;
    }

    // bisect zs_crit on -V over (0.001, zs_max); single fused reduction
    lo = 0.001f; hi = zs_max;
    for (int i = 0; i < 30; ++i) {
        float mid = 0.5f*(lo + hi);
        float fs, dfs; eval_fdf(C, mid, fs, dfs);
        float c4z = 4.f*frcp(mid);
        float t2z = 2.f*(1.f - mid);
        float comb = 0.f;
        if (act) {
            float ic = vc_point(C, mid, fs, y, omy2);
            float id = vd_point(C, mid, yd);
            comb = (W*ic)*c4z - (W2*id)*t2z;
        }
        float s = bsum(comb);
        float V = coef*PI_F*(s - t2z*0.0005f);
        if (-V < 0.f) hi = mid; else lo = mid;
    }
    float zs_crit = 0.5f*(lo + hi);

    float L_crit;
    {
        float fs, dfs; eval_fdf(C, zs_crit, fs, dfs);
        float inv_fs = frcp(fs);
        float s = bsum(act ? W*L_point(C, zs_crit, inv_fs, y, omy2, r4) : 0.f);
        L_crit = 4.f*zs_crit*s*INVPI_F;
    }

    if (tid == 0) {
        g_scal[0] = zs_max; g_scal[1] = L_max;
        g_scal[2] = zs_crit; g_scal[3] = L_crit;
    }
}

// ---------------------------------------------------------------------------
// Build L(zs) table: one warp per entry, full-chip parallel.
// ---------------------------------------------------------------------------
__global__ void __launch_bounds__(256) k_table(const float* a, const float* b)
{
    __shared__ float4 tab[NPTS];
    build_tab(tab);
    __syncthreads();

    Coefs C; make_coefs(a[0], a[1], b[0], b[1], C);
    int j = blockIdx.x*8 + (threadIdx.x >> 5);
    int lane = threadIdx.x & 31;
    float zs_max = g_scal[0];
    float dz = (zs_max - ZLO)*(1.f/(float)(TABN - 1));
    float zs = ZLO + dz*(float)j;
    float fs, dfs; eval_fdf(C, zs, fs, dfs);
    float inv_fs = frcp(fs);
    float sL = 0.f;
    for (int k = lane; k < NPTS; k += 32) {
        float4 t = tab[k];
        sL = fmaf(t.w, L_point(C, zs, inv_fs, t.x, t.y, t.z), sL);
    }
    #pragma unroll
    for (int o = 16; o; o >>= 1) sL += __shfl_xor_sync(0xffffffffu, sL, o);
    if (lane == 0) g_Ltab[j] = 4.f*zs*sL*INVPI_F;
}

// ---------------------------------------------------------------------------
// Phase B: one warp per element. Table inversion + 1 Newton polish + V.
// ---------------------------------------------------------------------------
__global__ void __launch_bounds__(256) k_solve(const float* __restrict__ Ls,
                                               const float* __restrict__ a,
                                               const float* __restrict__ b,
                                               const float* __restrict__ lc,
                                               float* __restrict__ out, int B)
{
    __shared__ float4 tab[NPTS];
    __shared__ float Lt[TABN];
    build_tab(tab);
    for (int i = threadIdx.x; i < TABN; i += blockDim.x) Lt[i] = g_Ltab[i];
    __syncthreads();

    int gw = blockIdx.x*8 + (threadIdx.x >> 5);
    if (gw >= B) return;
    int lane = threadIdx.x & 31;

    Coefs C; make_coefs(a[0], a[1], b[0], b[1], C);
    float zs_max = g_scal[0], L_crit = g_scal[3];
    float coef = expf(lc[0]);

    float Lq = Ls[gw];
    bool valid = Lq < L_crit;
    float Leff = valid ? Lq : 0.5f*L_crit;

    // invert L(zs) = Leff via binary search + linear interp on the shared table
    int lo = 0, hi = TABN - 1;
    #pragma unroll
    for (int s = 0; s < 12; ++s) {
        int mid = (lo + hi + 1) >> 1;
        if (Lt[mid] <= Leff) lo = mid; else hi = mid - 1;
    }
    float dz = (zs_max - ZLO)*(1.f/(float)(TABN - 1));
    float L0 = Lt[lo];
    float L1 = Lt[min(lo + 1, TABN - 1)];
    float fr = (Leff - L0)*frcp(fmaxf(L1 - L0, 1e-30f));
    fr = fminf(fmaxf(fr, 0.f), 1.f);
    float zs = ZLO + dz*((float)lo + fr);
    zs = fminf(fmaxf(zs, 1e-4f), 0.9995f);

    // one Newton polish step with the true quadrature L / dL
    {
        float fs, dfs; eval_fdf(C, zs, fs, dfs);
        float inv_fs = frcp(fs);
        float K12 = fmaf(zs*dfs, inv_fs, 2.f);
        float sL = 0.f, sD = 0.f;
        for (int k = lane; k < NPTS; k += 32) {
            float4 t = tab[k];
            float iL, idL;
            ldl_point(C, zs, inv_fs, K12, t.x, t.y, t.z, iL, idL);
            sL = fmaf(t.w, iL, sL);
            sD = fmaf(t.w, idL, sD);
        }
        #pragma unroll
        for (int o = 16; o; o >>= 1) {
            sL += __shfl_xor_sync(0xffffffffu, sL, o);
            sD += __shfl_xor_sync(0xffffffffu, sD, o);
        }
        float Lv  = 4.f*zs*sL*INVPI_F;
        float dLv = sD*(2.f*INVPI_F);
        float zn = zs - (Lv - Leff)*frcp(dLv);
        zs = fminf(fmaxf(zn, 1e-4f), 0.9995f);
    }

    // final V at the root (connected + disconnected fused in one pass)
    float fs, dfs; eval_fdf(C, zs, fs, dfs);
    const float h2 = 0.999f/999.f;
    float sC = 0.f, sD2 = 0.f;
    for (int k = lane; k < NPTS; k += 32) {
        float4 t = tab[k];
        sC = fmaf(t.w, vc_point(C, zs, fs, t.x, t.y), sC);
        float y2 = 0.001f + h2*(float)k;
        float W2 = (k == 0) ? (0.0005f + 0.5f*h2) : ((k == 999) ? 0.5f*h2 : h2);
        sD2 = fmaf(W2, vd_point(C, zs, y2), sD2);
    }
    #pragma unroll
    for (int o = 16; o; o >>= 1) {
        sC  += __shfl_xor_sync(0xffffffffu, sC,  o);
        sD2 += __shfl_xor_sync(0xffffffffu, sD2, o);
    }
    sD2 += 0.0005f;   // prepended "1" sample of the disconnected trapz
    float Vc = coef*PI_F*4.f*sC/zs;
    float Vd = coef*PI_F*2.f*(1.f - zs)*sD2;

    if (lane == 0) out[gw] = valid ? (Vc - Vd) : 0.f;
}

extern "C" void kernel_launch(void* const* d_in, const int* in_sizes, int n_in,
                              void* d_out, int out_size)
{
    const float* Ls = (const float*)d_in[0];
    const float* a  = (const float*)d_in[1];
    const float* b  = (const float*)d_in[2];
    const float* lc = (const float*)d_in[3];
    float* out = (float*)d_out;
    int B = in_sizes[0];

    k_precompute<<<1, 1024>>>(a, b, lc);
    k_table<<<TABN/8, 256>>>(a, b);
    int blocks = (B + 7)/8;
    if (blocks > 0)
        k_solve<<<blocks, 256>>>(Ls, a, b, lc, out, B);
}

// round 4
// speedup vs baseline: 10.8382x; 2.1730x over previous
#include <cuda_runtime.h>
#include <math.h>

#define PI_F     3.14159265358979f
#define INVPI_F  0.3183098861837907f
#define EPS_F    1e-12f
#define NPTS     1000
#define TABN     2048
#define ZLO      1e-4f
#define ZHI      0.9995f
#define DZ       ((ZHI - ZLO) / (float)(TABN - 1))
#define LN2_F    0.69314718055994531f

__device__ float g_L[TABN];
__device__ float g_dL[TABN];
__device__ float g_V[TABN];
__device__ float g_scal[4];   // zs_max, zs_crit, L_crit
__device__ int   g_jmax;

struct Coefs {
    float F1, F2, F3, F4, FLln2;   // f(z) = 1 + F1 z + ... + F4 z^4 + (FLln2*z^4)*lg2(z)
    float Q1, Q2, Q3, Q4;          // q(z) = -4 + Q1 z + ...; z*df = 4f + q
    float c1, c2, c3;              // bp(z) = 1 + c1 z + c2 z^2 + c3 z^3; B = bp^2
    float d2, d3;                  // bp'(z) = c1 + d2 z + d3 z^2
};

static __device__ __forceinline__ float frcp(float x){ float r; asm("rcp.approx.f32 %0,%1;"   : "=f"(r) : "f"(x)); return r; }
static __device__ __forceinline__ float frsq(float x){ float r; asm("rsqrt.approx.f32 %0,%1;" : "=f"(r) : "f"(x)); return r; }
static __device__ __forceinline__ float fsqt(float x){ float r; asm("sqrt.approx.f32 %0,%1;"  : "=f"(r) : "f"(x)); return r; }
static __device__ __forceinline__ float flg2(float x){ float r; asm("lg2.approx.f32 %0,%1;"   : "=f"(r) : "f"(x)); return r; }

static __device__ __forceinline__ void make_coefs(float a0, float a1, float b0, float b1, Coefs& C)
{
    float w1 = 2.f*a0;
    float w2 = fmaf(a0, a0, 2.f*a1);
    float w3 = 2.f*a0*a1;
    float w4 = a1*a1;
    C.F1 = (4.f/3.f)*w1;
    C.F2 = 2.f*w2;
    C.F3 = 4.f*w3;
    C.F4 = -(1.f + C.F1 + C.F2 + C.F3);   // f(1)=0 identity
    float FL = -4.f*w4;
    C.FLln2 = FL * LN2_F;
    C.Q1 = -4.f*w1; C.Q2 = -4.f*w2; C.Q3 = -4.f*w3; C.Q4 = FL;
    C.c1 = b0; C.c2 = b1;
    C.c3 = ((a0 + a1) - b0) - b1;
    C.d2 = 2.f*C.c2; C.d3 = 3.f*C.c3;
}

static __device__ __forceinline__ float evalf(const Coefs& C, float z, float& z2, float& z4)
{
    z2 = z*z; z4 = z2*z2;
    float p = fmaf(fmaf(fmaf(fmaf(C.F4, z, C.F3), z, C.F2), z, C.F1), z, 1.f);
    return fmaf(C.FLln2*z4, flg2(z), p);
}

static __device__ __forceinline__ void eval_fdf(const Coefs& C, float z, float& f, float& df)
{
    float z2, z4; f = evalf(C, z, z2, z4);
    float q = fmaf(fmaf(fmaf(fmaf(C.Q4, z, C.Q3), z, C.Q2), z, C.Q1), z, -4.f);
    df = fmaf(4.f, f, q) * frcp(z);
}

// Fused L + dL + Vc integrands at one quadrature point (shared f, bp, D).
static __device__ __forceinline__ void ldlv_point(const Coefs& C, float zs, float fs, float inv_fs,
                                                  float K12, float y, float omy2, float r4,
                                                  float& iL, float& idL, float& iVc)
{
    float z = zs*omy2;
    float z2, z4; float f = evalf(C, z, z2, z4);
    float q = fmaf(fmaf(fmaf(fmaf(C.Q4, z, C.Q3), z, C.Q2), z, C.Q1), z, -4.f);
    float t4 = fmaf(4.f, f, q);                       // z*df
    float fr = f*inv_fs;
    float r4fr = r4*fr;
    float m = fmaxf(r4fr - 1.f, EPS_F);
    float rm = frsq(m);
    float bp  = fmaf(fmaf(fmaf(C.c3, z, C.c2), z, C.c1), z, 1.f);
    float dbp = fmaf(fmaf(C.d3, z, C.d2), z, C.c1);
    float Dd = (1.f - z2)*(1.f + z2);                 // 1 - z^4
    float rsq = frsq(Dd);
    float invD = rsq*rsq;
    float sg = bp*rsq;                                // sqrt(g)
    iL = sg*rm*y;
    float zdgg = fmaf(2.f*z*dbp, frcp(bp), 4.f*(z4*invD));   // z*dg/g
    float A1 = r4fr*(K12 + zdgg);
    float A2 = t4*(r4*inv_fs);                        // zs^4/z^3 * df/fs
    float brk = (A1 - A2) - (2.f + zdgg);
    idL = brk*iL*(rm*rm);                             // /2 folded into 2/pi
    // connected V piece
    float fg = fmaxf(f*(bp*bp)*invD, EPS_F);
    float sfg = fsqt(fg);
    float w = omy2*omy2;
    float tt = fmaxf(fmaf(-(w*w)*fs, frcp(f), 1.f), EPS_F);  // 1 - w^2*fs/f
    iVc = sfg*frcp(w)*(frsq(tt) - 1.f)*y;
}

// V connected integrand alone (per-element final V)
static __device__ __forceinline__ float vc_point(const Coefs& C, float zs, float fs,
                                                 float y, float omy2)
{
    float z = zs*omy2;
    float z2, z4; float f = evalf(C, z, z2, z4);
    float bp = fmaf(fmaf(fmaf(C.c3, z, C.c2), z, C.c1), z, 1.f);
    float Dd = (1.f - z2)*(1.f + z2);
    float rsq = frsq(Dd);
    float invD = rsq*rsq;
    float fg = fmaxf(f*(bp*bp)*invD, EPS_F);
    float sfg = fsqt(fg);
    float w = omy2*omy2;
    float tt = fmaxf(fmaf(-(w*w)*fs, frcp(f), 1.f), EPS_F);
    return sfg*frcp(w)*(frsq(tt) - 1.f)*y;
}

// V disconnected integrand (own grid y2 on [0.001, 1.0])
static __device__ __forceinline__ float vd_point(const Coefs& C, float zs, float y2)
{
    float z = fmaf(zs - 1.f, y2, 1.f);                // 1 - (1-zs)*y2
    float z2, z4; float f = evalf(C, z, z2, z4);
    float bp = fmaf(fmaf(fmaf(C.c3, z, C.c2), z, C.c1), z, 1.f);
    float Dd = (1.f - z2)*(1.f + z2);
    float rsq = frsq(Dd);
    float invD = rsq*rsq;
    float fg = fmaxf(f*(bp*bp)*invD, EPS_F);
    float rz = frcp(z);
    return fsqt(fg)*(rz*rz);
}

// Quadrature table: y, (1-y)(1+y), r4 = (1-y^2)^-4, trapz weight (endpoint
// weights fold the reference's _extend extrapolation in closed form).
static __device__ void build_tab(float4* tab)
{
    const float h = 0.998f/999.f;
    for (int k = threadIdx.x; k < NPTS; k += blockDim.x) {
        float y = 0.001f + h*(float)k;
        float omy2 = (1.f - y)*(1.f + y);
        float t2 = omy2*omy2;
        float r4 = 1.f/(t2*t2);
        float W = h;
        if      (k == 0)   W = 0.5f*h + 0.001f + 0.5f*(1.0e-6f)/h;
        else if (k == 1)   W = h - 0.5f*(1.0e-6f)/h;
        else if (k == 999) W = 0.5f*h + 0.5f*(1.f - y);
        tab[k] = make_float4(y, omy2, r4, W);
    }
}

// ---------------------------------------------------------------------------
// k_table: one warp per grid zs; fused L / dL / V quadrature.
// ---------------------------------------------------------------------------
__global__ void __launch_bounds__(256) k_table(const float* a, const float* b, const float* lc)
{
    __shared__ float4 tab[NPTS];
    build_tab(tab);
    __syncthreads();

    Coefs C; make_coefs(a[0], a[1], b[0], b[1], C);
    float coef = expf(lc[0]);

    int j = blockIdx.x*8 + (threadIdx.x >> 5);
    int lane = threadIdx.x & 31;
    float zs = ZLO + DZ*(float)j;

    float fs, dfs; eval_fdf(C, zs, fs, dfs);
    float inv_fs = frcp(fs);
    float K12 = fmaf(zs*dfs, inv_fs, 2.f);

    const float h2 = 0.999f/999.f;
    float sL = 0.f, sD = 0.f, sC = 0.f, sD2 = 0.f;
    for (int k = lane; k < NPTS; k += 32) {
        float4 t = tab[k];
        float iL, idL, iVc;
        ldlv_point(C, zs, fs, inv_fs, K12, t.x, t.y, t.z, iL, idL, iVc);
        sL = fmaf(t.w, iL, sL);
        sD = fmaf(t.w, idL, sD);
        sC = fmaf(t.w, iVc, sC);
        float y2 = 0.001f + h2*(float)k;
        float W2 = (k == 0) ? (0.0005f + 0.5f*h2) : ((k == 999) ? 0.5f*h2 : h2);
        sD2 = fmaf(W2, vd_point(C, zs, y2), sD2);
    }
    #pragma unroll
    for (int o = 16; o; o >>= 1) {
        sL  += __shfl_xor_sync(0xffffffffu, sL,  o);
        sD  += __shfl_xor_sync(0xffffffffu, sD,  o);
        sC  += __shfl_xor_sync(0xffffffffu, sC,  o);
        sD2 += __shfl_xor_sync(0xffffffffu, sD2, o);
    }
    if (lane == 0) {
        g_L[j]  = 4.f*zs*sL*INVPI_F;
        g_dL[j] = sD*(2.f*INVPI_F);
        float Vc = coef*PI_F*4.f*sC/zs;
        float Vd = coef*PI_F*2.f*(1.f - zs)*(sD2 + 0.0005f);
        g_V[j]  = Vc - Vd;   // used ONLY for zs_crit crossing (mid-range zs)
    }
}

// ---------------------------------------------------------------------------
// k_scal: jmax (dL sign change), zs_crit (first V <=0 -> >0 crossing), L_crit.
// ---------------------------------------------------------------------------
__global__ void __launch_bounds__(1024) k_scal()
{
    __shared__ int s_jmax, s_jcrit;
    int tid = threadIdx.x;
    if (tid == 0) { s_jmax = TABN - 1; s_jcrit = TABN; }
    __syncthreads();

    for (int j = tid; j < TABN - 1; j += 1024)
        if (g_dL[j] >= 0.f && g_dL[j+1] < 0.f) atomicMin(&s_jmax, j);
    __syncthreads();
    int jmax = s_jmax;

    int j001 = (int)ceilf((0.001f - ZLO)/DZ);
    for (int j = tid; j < jmax; j += 1024)
        if (j >= j001 && g_V[j] <= 0.f && g_V[j+1] > 0.f) atomicMin(&s_jcrit, j);
    __syncthreads();

    if (tid == 0) {
        float zs_max;
        if (jmax < TABN - 1) {
            float d0 = g_dL[jmax], d1 = g_dL[jmax+1];
            float t = d0 / fmaxf(d0 - d1, 1e-30f);
            zs_max = ZLO + DZ*((float)jmax + fminf(fmaxf(t, 0.f), 1.f));
        } else zs_max = ZHI;

        int jc = (s_jcrit < TABN) ? s_jcrit : (jmax - 1);
        float V0 = g_V[jc], V1 = g_V[jc+1];
        float t = (-V0) / fmaxf(V1 - V0, 1e-30f);
        t = fminf(fmaxf(t, 0.f), 1.f);
        float zs_crit = ZLO + DZ*((float)jc + t);
        float L0 = g_L[jc], L1 = g_L[jc+1];
        float m0 = DZ*g_dL[jc], m1 = DZ*g_dL[jc+1];
        float d = L1 - L0;
        float c2 = 3.f*d - 2.f*m0 - m1;
        float c3 = m0 + m1 - 2.f*d;
        float L_crit = ((c3*t + c2)*t + m0)*t + L0;

        g_scal[0] = zs_max; g_scal[1] = zs_crit; g_scal[2] = L_crit;
        g_jmax = (jmax > 0) ? jmax : 1;
    }
}

// ---------------------------------------------------------------------------
// k_solve: one WARP per element. Table inversion for zs (cheap, lane-uniform)
// then a real warp quadrature for V at that zs (same math that passed R2).
// ---------------------------------------------------------------------------
__global__ void __launch_bounds__(256) k_solve(const float* __restrict__ Ls,
                                               const float* __restrict__ a,
                                               const float* __restrict__ b,
                                               const float* __restrict__ lc,
                                               float* __restrict__ out, int B)
{
    __shared__ float4 tab[NPTS];
    __shared__ float Lt[TABN];
    __shared__ float dLt[TABN];
    build_tab(tab);
    for (int i = threadIdx.x; i < TABN; i += 256) { Lt[i] = g_L[i]; dLt[i] = g_dL[i]; }
    __syncthreads();

    int gw = blockIdx.x*8 + (threadIdx.x >> 5);
    if (gw >= B) return;
    int lane = threadIdx.x & 31;

    Coefs C; make_coefs(a[0], a[1], b[0], b[1], C);
    float L_crit = g_scal[2];
    int jmax = g_jmax;
    float coef = expf(lc[0]);

    float Lq = Ls[gw];
    bool valid = Lq < L_crit;
    float Leff = valid ? Lq : 0.5f*L_crit;

    // binary search for cell: largest j in [0, jmax-1] with Lt[j] <= Leff
    int lo = 0, hi = jmax;
    #pragma unroll
    for (int s = 0; s < 11; ++s) {
        int mid = (lo + hi) >> 1;
        bool c = (Lt[mid] <= Leff);
        lo = c ? mid : lo;
        hi = c ? hi : mid;
    }
    int j = lo;

    // Hermite inversion inside cell j (nodes + exact derivatives)
    float L0 = Lt[j], L1 = Lt[j+1];
    float m0 = DZ*dLt[j], m1 = DZ*dLt[j+1];
    float d = L1 - L0;
    float c2 = 3.f*d - 2.f*m0 - m1;
    float c3 = m0 + m1 - 2.f*d;
    float t = (Leff - L0)*frcp(fmaxf(d, 1e-30f));
    t = fminf(fmaxf(t, 0.f), 1.f);
    #pragma unroll
    for (int it = 0; it < 3; ++it) {
        float H  = ((c3*t + c2)*t + m0)*t + L0 - Leff;
        float Hp = (3.f*c3*t + 2.f*c2)*t + m0;
        t = t - H*frcp(Hp);
        t = fminf(fmaxf(t, 0.f), 1.f);
    }
    float zs = ZLO + DZ*((float)j + t);
    zs = fminf(fmaxf(zs, 1e-4f), 0.9995f);

    // per-element V quadrature (connected + disconnected in one pass)
    float fs, dfs; eval_fdf(C, zs, fs, dfs);
    const float h2 = 0.999f/999.f;
    float sC = 0.f, sD2 = 0.f;
    for (int k = lane; k < NPTS; k += 32) {
        float4 tt = tab[k];
        sC = fmaf(tt.w, vc_point(C, zs, fs, tt.x, tt.y), sC);
        float y2 = 0.001f + h2*(float)k;
        float W2 = (k == 0) ? (0.0005f + 0.5f*h2) : ((k == 999) ? 0.5f*h2 : h2);
        sD2 = fmaf(W2, vd_point(C, zs, y2), sD2);
    }
    #pragma unroll
    for (int o = 16; o; o >>= 1) {
        sC  += __shfl_xor_sync(0xffffffffu, sC,  o);
        sD2 += __shfl_xor_sync(0xffffffffu, sD2, o);
    }
    sD2 += 0.0005f;   // prepended "1" sample of the disconnected trapz
    float Vc = coef*PI_F*4.f*sC/zs;
    float Vd = coef*PI_F*2.f*(1.f - zs)*sD2;

    if (lane == 0) out[gw] = valid ? (Vc - Vd) : 0.f;
}

extern "C" void kernel_launch(void* const* d_in, const int* in_sizes, int n_in,
                              void* d_out, int out_size)
{
    const float* Ls = (const float*)d_in[0];
    const float* a  = (const float*)d_in[1];
    const float* b  = (const float*)d_in[2];
    const float* lc = (const float*)d_in[3];
    float* out = (float*)d_out;
    int B = in_sizes[0];

    k_table<<<TABN/8, 256>>>(a, b, lc);
    k_scal<<<1, 1024>>>();
    int blocks = (B + 7)/8;
    if (blocks > 0)
        k_solve<<<blocks, 256>>>(Ls, a, b, lc, out, B);
}

// round 6
// speedup vs baseline: 14.8364x; 1.3689x over previous
#include <cuda_runtime.h>
#include <math.h>

#define PI_F     3.14159265358979f
#define INVPI_F  0.3183098861837907f
#define EPS_F    1e-12f
#define NPTS     1000
#define KTAIL    64                 // last KTAIL disconnected-grid terms: exact per element
#define KSPLIT   (NPTS - KTAIL)     // 936
#define TABN     2048
#define ZLO      1e-4f
#define ZHI      0.9995f
#define DZ       ((ZHI - ZLO) / (float)(TABN - 1))
#define LN2_F    0.69314718055994531f

__device__ float g_L[TABN];
__device__ float g_dL[TABN];
__device__ float g_sC[TABN];   // connected reduced integral (smooth in zs)
__device__ float g_H[TABN];    // disconnected sum, k < KSPLIT only (smooth in zs)
__device__ float g_V[TABN];    // full V at nodes (for zs_crit sign crossing only)

struct Coefs {
    float F1, F2, F3, F4, FLln2;   // f(z) = 1 + F1 z + ... + F4 z^4 + (FLln2*z^4)*lg2(z)
    float Q1, Q2, Q3, Q4;          // q(z) = -4 + Q1 z + ...; z*df = 4f + q
    float c1, c2, c3;              // bp(z) = 1 + c1 z + c2 z^2 + c3 z^3; B = bp^2
    float d2, d3;                  // bp'(z) = c1 + d2 z + d3 z^2
};

static __device__ __forceinline__ float frcp(float x){ float r; asm("rcp.approx.f32 %0,%1;"   : "=f"(r) : "f"(x)); return r; }
static __device__ __forceinline__ float frsq(float x){ float r; asm("rsqrt.approx.f32 %0,%1;" : "=f"(r) : "f"(x)); return r; }
static __device__ __forceinline__ float fsqt(float x){ float r; asm("sqrt.approx.f32 %0,%1;"  : "=f"(r) : "f"(x)); return r; }
static __device__ __forceinline__ float flg2(float x){ float r; asm("lg2.approx.f32 %0,%1;"   : "=f"(r) : "f"(x)); return r; }

static __device__ __forceinline__ void make_coefs(float a0, float a1, float b0, float b1, Coefs& C)
{
    float w1 = 2.f*a0;
    float w2 = fmaf(a0, a0, 2.f*a1);
    float w3 = 2.f*a0*a1;
    float w4 = a1*a1;
    C.F1 = (4.f/3.f)*w1;
    C.F2 = 2.f*w2;
    C.F3 = 4.f*w3;
    C.F4 = -(1.f + C.F1 + C.F2 + C.F3);   // f(1)=0 identity
    float FL = -4.f*w4;
    C.FLln2 = FL * LN2_F;
    C.Q1 = -4.f*w1; C.Q2 = -4.f*w2; C.Q3 = -4.f*w3; C.Q4 = FL;
    C.c1 = b0; C.c2 = b1;
    C.c3 = ((a0 + a1) - b0) - b1;
    C.d2 = 2.f*C.c2; C.d3 = 3.f*C.c3;
}

static __device__ __forceinline__ float evalf(const Coefs& C, float z, float& z2, float& z4)
{
    z2 = z*z; z4 = z2*z2;
    float p = fmaf(fmaf(fmaf(fmaf(C.F4, z, C.F3), z, C.F2), z, C.F1), z, 1.f);
    return fmaf(C.FLln2*z4, flg2(z), p);
}

static __device__ __forceinline__ void eval_fdf(const Coefs& C, float z, float& f, float& df)
{
    float z2, z4; f = evalf(C, z, z2, z4);
    float q = fmaf(fmaf(fmaf(fmaf(C.Q4, z, C.Q3), z, C.Q2), z, C.Q1), z, -4.f);
    df = fmaf(4.f, f, q) * frcp(z);
}

// Fused L + dL + Vc integrands at one quadrature point (shared f, bp, D).
static __device__ __forceinline__ void ldlv_point(const Coefs& C, float zs, float fs, float inv_fs,
                                                  float K12, float y, float omy2, float inv_w,
                                                  float& iL, float& idL, float& iVc)
{
    float r4 = inv_w*inv_w;
    float z = zs*omy2;
    float z2, z4; float f = evalf(C, z, z2, z4);
    float q = fmaf(fmaf(fmaf(fmaf(C.Q4, z, C.Q3), z, C.Q2), z, C.Q1), z, -4.f);
    float t4 = fmaf(4.f, f, q);                       // z*df
    float fr = f*inv_fs;
    float r4fr = r4*fr;
    float m = fmaxf(r4fr - 1.f, EPS_F);
    float rm = frsq(m);
    float bp  = fmaf(fmaf(fmaf(C.c3, z, C.c2), z, C.c1), z, 1.f);
    float dbp = fmaf(fmaf(C.d3, z, C.d2), z, C.c1);
    float Dd = (1.f - z2)*(1.f + z2);                 // 1 - z^4
    float rsq = frsq(Dd);
    float invD = rsq*rsq;
    float sg = bp*rsq;                                // sqrt(g)
    iL = sg*rm*y;
    float zdgg = fmaf(2.f*z*dbp, frcp(bp), 4.f*(z4*invD));   // z*dg/g
    float A1 = r4fr*(K12 + zdgg);
    float A2 = t4*(r4*inv_fs);                        // zs^4/z^3 * df/fs
    float brk = (A1 - A2) - (2.f + zdgg);
    idL = brk*iL*(rm*rm);                             // /2 folded into 2/pi
    // connected V piece
    float fg = fmaxf(f*(bp*bp)*invD, EPS_F);
    float sfg = fsqt(fg);
    float w2 = omy2*omy2; w2 = w2*w2;                 // w^2 = (1-y^2)^4
    float tt = fmaxf(fmaf(-w2*fs, frcp(f), 1.f), EPS_F);  // 1 - w^2*fs/f
    iVc = sfg*inv_w*(frsq(tt) - 1.f)*y;
}

// V disconnected integrand (own grid y2 on [0.001, 1.0])
static __device__ __forceinline__ float vd_point(const Coefs& C, float zs, float y2)
{
    float z = fmaf(zs - 1.f, y2, 1.f);                // 1 - (1-zs)*y2
    float z2, z4; float f = evalf(C, z, z2, z4);
    float bp = fmaf(fmaf(fmaf(C.c3, z, C.c2), z, C.c1), z, 1.f);
    float Dd = (1.f - z2)*(1.f + z2);
    float rsq = frsq(Dd);
    float invD = rsq*rsq;
    float fg = fmaxf(f*(bp*bp)*invD, EPS_F);
    float rz = frcp(z);
    return fsqt(fg)*(rz*rz);
}

// Exact tail of the disconnected trapz (last KTAIL points of the y2 grid).
static __device__ __forceinline__ float vd_tail(const Coefs& C, float zs)
{
    const float h2 = 0.999f/999.f;
    float s = 0.f;
    #pragma unroll 4
    for (int k = KSPLIT; k < NPTS; ++k) {
        float y2 = 0.001f + h2*(float)k;
        float W2 = (k == NPTS-1) ? 0.5f*h2 : h2;
        s = fmaf(W2, vd_point(C, zs, y2), s);
    }
    return s;
}

// Quadrature table: y, (1-y)(1+y), inv_w = (1-y^2)^-2, trapz weight (endpoint
// weights fold the reference's _extend extrapolation in closed form).
static __device__ void build_tab(float4* tab)
{
    const float h = 0.998f/999.f;
    for (int k = threadIdx.x; k < NPTS; k += blockDim.x) {
        float y = 0.001f + h*(float)k;
        float omy2 = (1.f - y)*(1.f + y);
        float inv_w = 1.f/(omy2*omy2);
        float W = h;
        if      (k == 0)   W = 0.5f*h + 0.001f + 0.5f*(1.0e-6f)/h;
        else if (k == 1)   W = h - 0.5f*(1.0e-6f)/h;
        else if (k == 999) W = 0.5f*h + 0.5f*(1.f - y);
        tab[k] = make_float4(y, omy2, inv_w, W);
    }
}

// ---------------------------------------------------------------------------
// k_table: one warp per grid zs (4/block, 512 blocks).
// ---------------------------------------------------------------------------
__global__ void __launch_bounds__(128) k_table(const float* __restrict__ a,
                                               const float* __restrict__ b,
                                               const float* __restrict__ lc)
{
    __shared__ float4 tab[NPTS];
    build_tab(tab);
    __syncthreads();

    Coefs C; make_coefs(a[0], a[1], b[0], b[1], C);
    float coef = expf(lc[0]);

    int j = blockIdx.x*4 + (threadIdx.x >> 5);
    int lane = threadIdx.x & 31;
    float zs = ZLO + DZ*(float)j;

    float fs, dfs; eval_fdf(C, zs, fs, dfs);
    float inv_fs = frcp(fs);
    float K12 = fmaf(zs*dfs, inv_fs, 2.f);

    const float h2 = 0.999f/999.f;
    float sL = 0.f, sD = 0.f, sC = 0.f, sH = 0.f, sT = 0.f;
    for (int k = lane; k < NPTS; k += 32) {
        float4 t = tab[k];
        float iL, idL, iVc;
        ldlv_point(C, zs, fs, inv_fs, K12, t.x, t.y, t.z, iL, idL, iVc);
        sL = fmaf(t.w, iL, sL);
        sD = fmaf(t.w, idL, sD);
        sC = fmaf(t.w, iVc, sC);
        float y2 = 0.001f + h2*(float)k;
        float W2 = (k == 0) ? (0.0005f + 0.5f*h2) : ((k == 999) ? 0.5f*h2 : h2);
        float vd = W2*vd_point(C, zs, y2);
        if (k < KSPLIT) sH += vd; else sT += vd;
    }
    #pragma unroll
    for (int o = 16; o; o >>= 1) {
        sL += __shfl_xor_sync(0xffffffffu, sL, o);
        sD += __shfl_xor_sync(0xffffffffu, sD, o);
        sC += __shfl_xor_sync(0xffffffffu, sC, o);
        sH += __shfl_xor_sync(0xffffffffu, sH, o);
        sT += __shfl_xor_sync(0xffffffffu, sT, o);
    }
    if (lane == 0) {
        g_L[j]  = 4.f*zs*sL*INVPI_F;
        g_dL[j] = sD*(2.f*INVPI_F);
        g_sC[j] = sC;
        g_H[j]  = sH;
        // full node V (used only for the zs_crit sign crossing)
        float Vc = coef*PI_F*4.f*sC/zs;
        float Vd = coef*PI_F*2.f*(1.f - zs)*((sH + sT) + 0.0005f);
        g_V[j]  = Vc - Vd;
    }
}

// Catmull-Rom interpolation helper on a shared table at cell (j, t).
static __device__ __forceinline__ float cr_interp(const float* T, int j, float t)
{
    float V0 = T[j], V1 = T[j+1];
    float Vm = (j > 0) ? T[j-1] : V0;
    float Vp = (j+2 < TABN) ? T[j+2] : V1;
    float dv = V1 - V0;
    float m0 = (j > 0) ? 0.5f*(V1 - Vm) : dv;
    float m1 = (j+2 < TABN) ? 0.5f*(Vp - V0) : dv;
    float e2 = 3.f*dv - 2.f*m0 - m1;
    float e3 = m0 + m1 - 2.f*dv;
    return ((e3*t + e2)*t + m0)*t + V0;
}

// ---------------------------------------------------------------------------
// k_solve: per-block scalar scan (jmax, jcrit -> L_crit), then one THREAD per
// element: L-table inversion for zs; V = exact 1/zs * interp(sC)
//          - exact (1-zs) * (interp(H) + exact 64-term tail).
// ---------------------------------------------------------------------------
__global__ void __launch_bounds__(256) k_solve(const float* __restrict__ Ls,
                                               const float* __restrict__ a,
                                               const float* __restrict__ b,
                                               const float* __restrict__ lc,
                                               float* __restrict__ out, int B)
{
    __shared__ float Lt[TABN];
    __shared__ float dLt[TABN];
    __shared__ float sCt[TABN];
    __shared__ float Ht[TABN];
    __shared__ int s_jmax, s_jcrit;
    __shared__ float s_Lcrit;

    int tid = threadIdx.x;
    if (tid == 0) { s_jmax = TABN - 1; s_jcrit = TABN; }
    for (int i = tid; i < TABN; i += 256) {
        Lt[i] = g_L[i]; dLt[i] = g_dL[i]; sCt[i] = g_sC[i]; Ht[i] = g_H[i];
    }
    __syncthreads();

    // jmax: first dL sign change + -> -
    for (int j = tid; j < TABN - 1; j += 256)
        if (dLt[j] >= 0.f && dLt[j+1] < 0.f) atomicMin(&s_jmax, j);
    __syncthreads();
    int jmax = s_jmax;
    if (jmax < 1) jmax = 1;

    // jcrit: first V crossing <=0 -> >0 for zs >= 0.001 (node V from gmem)
    int j001 = (int)ceilf((0.001f - ZLO)/DZ);
    for (int j = tid; j < jmax; j += 256)
        if (j >= j001 && g_V[j] <= 0.f && g_V[j+1] > 0.f) atomicMin(&s_jcrit, j);
    __syncthreads();

    if (tid == 0) {
        int jc = (s_jcrit < TABN) ? s_jcrit : (jmax - 1);
        if (jc < 0) jc = 0;
        float V0 = g_V[jc], V1 = g_V[jc+1];
        float t = (-V0) / fmaxf(V1 - V0, 1e-30f);
        t = fminf(fmaxf(t, 0.f), 1.f);
        float L0 = Lt[jc], L1 = Lt[jc+1];
        float m0 = DZ*dLt[jc], m1 = DZ*dLt[jc+1];
        float d = L1 - L0;
        float c2 = 3.f*d - 2.f*m0 - m1;
        float c3 = m0 + m1 - 2.f*d;
        s_Lcrit = ((c3*t + c2)*t + m0)*t + L0;
    }
    __syncthreads();
    float L_crit = s_Lcrit;

    int i = blockIdx.x*256 + tid;
    if (i >= B) return;

    Coefs C; make_coefs(a[0], a[1], b[0], b[1], C);
    float coef = expf(lc[0]);

    float Lq = Ls[i];
    bool valid = Lq < L_crit;
    float Leff = valid ? Lq : 0.5f*L_crit;

    // binary search: largest j in [0, jmax-1] with Lt[j] <= Leff
    int lo = 0, hi = jmax;
    #pragma unroll
    for (int s = 0; s < 11; ++s) {
        int mid = (lo + hi) >> 1;
        bool c = (Lt[mid] <= Leff);
        lo = c ? mid : lo;
        hi = c ? hi : mid;
    }
    int j = lo;

    // Hermite inversion inside cell j (nodes + exact derivatives)
    float L0 = Lt[j], L1 = Lt[j+1];
    float m0 = DZ*dLt[j], m1 = DZ*dLt[j+1];
    float d = L1 - L0;
    float c2 = 3.f*d - 2.f*m0 - m1;
    float c3 = m0 + m1 - 2.f*d;
    float t = (Leff - L0)*frcp(fmaxf(d, 1e-30f));
    t = fminf(fmaxf(t, 0.f), 1.f);
    #pragma unroll
    for (int it = 0; it < 3; ++it) {
        float H  = ((c3*t + c2)*t + m0)*t + L0 - Leff;
        float Hp = (3.f*c3*t + 2.f*c2)*t + m0;
        t = t - H*frcp(Hp);
        t = fminf(fmaxf(t, 0.f), 1.f);
    }
    float zs = ZLO + DZ*((float)j + t);
    zs = fminf(fmaxf(zs, 1e-4f), 0.9995f);

    // assemble V: smooth parts interpolated, singular parts exact
    float sC = cr_interp(sCt, j, t);
    float sH = cr_interp(Ht,  j, t);
    float tail = vd_tail(C, zs);
    float Vc = coef*PI_F*4.f*sC/zs;
    float Vd = coef*PI_F*2.f*(1.f - zs)*((sH + tail) + 0.0005f);
    float V = Vc - Vd;

    out[i] = valid ? V : 0.f;
}

extern "C" void kernel_launch(void* const* d_in, const int* in_sizes, int n_in,
                              void* d_out, int out_size)
{
    const float* Ls = (const float*)d_in[0];
    const float* a  = (const float*)d_in[1];
    const float* b  = (const float*)d_in[2];
    const float* lc = (const float*)d_in[3];
    float* out = (float*)d_out;
    int B = in_sizes[0];

    k_table<<<TABN/4, 128>>>(a, b, lc);
    int blocks = (B + 255)/256;
    if (blocks > 0)
        k_solve<<<blocks, 256>>>(Ls, a, b, lc, out, B);
}

// round 7
// speedup vs baseline: 15.8857x; 1.0707x over previous
#include <cuda_runtime.h>
#include <math.h>

#define PI_F     3.14159265358979f
#define INVPI_F  0.3183098861837907f
#define EPS_F    1e-12f
#define NPTS     1000
#define KTAIL    64                 // last KTAIL disconnected-grid terms: exact per element
#define KSPLIT   (NPTS - KTAIL)     // 936
#define TABN     2048
#define ZLO      1e-4f
#define ZHI      0.9995f
#define DZ       ((ZHI - ZLO) / (float)(TABN - 1))
#define LN2_F    0.69314718055994531f

__device__ float g_L[TABN];
__device__ float g_dL[TABN];
__device__ float g_sC[TABN];   // connected reduced integral (smooth in zs)
__device__ float g_H[TABN];    // disconnected sum, k < KSPLIT only (smooth in zs)
__device__ float g_V[TABN];    // full V at nodes (zs_crit sign crossing only)
__device__ float g_Lcrit;
__device__ int   g_jmax;

struct Coefs {
    float F1, F2, F3, F4, FLln2;   // f(z) = 1 + F1 z + ... + F4 z^4 + (FLln2*z^4)*lg2(z)
    float Q1, Q2, Q3, Q4;          // q(z) = -4 + Q1 z + ...; z*df = 4f + q
    float c1, c2, c3;              // bp(z) = 1 + c1 z + c2 z^2 + c3 z^3; B = bp^2
    float d2, d3;                  // bp'(z) = c1 + d2 z + d3 z^2
};

static __device__ __forceinline__ float frcp(float x){ float r; asm("rcp.approx.f32 %0,%1;"   : "=f"(r) : "f"(x)); return r; }
static __device__ __forceinline__ float frsq(float x){ float r; asm("rsqrt.approx.f32 %0,%1;" : "=f"(r) : "f"(x)); return r; }
static __device__ __forceinline__ float fsqt(float x){ float r; asm("sqrt.approx.f32 %0,%1;"  : "=f"(r) : "f"(x)); return r; }
static __device__ __forceinline__ float flg2(float x){ float r; asm("lg2.approx.f32 %0,%1;"   : "=f"(r) : "f"(x)); return r; }

static __device__ __forceinline__ void make_coefs(float a0, float a1, float b0, float b1, Coefs& C)
{
    float w1 = 2.f*a0;
    float w2 = fmaf(a0, a0, 2.f*a1);
    float w3 = 2.f*a0*a1;
    float w4 = a1*a1;
    C.F1 = (4.f/3.f)*w1;
    C.F2 = 2.f*w2;
    C.F3 = 4.f*w3;
    C.F4 = -(1.f + C.F1 + C.F2 + C.F3);   // f(1)=0 identity
    float FL = -4.f*w4;
    C.FLln2 = FL * LN2_F;
    C.Q1 = -4.f*w1; C.Q2 = -4.f*w2; C.Q3 = -4.f*w3; C.Q4 = FL;
    C.c1 = b0; C.c2 = b1;
    C.c3 = ((a0 + a1) - b0) - b1;
    C.d2 = 2.f*C.c2; C.d3 = 3.f*C.c3;
}

static __device__ __forceinline__ float evalf(const Coefs& C, float z, float& z2, float& z4)
{
    z2 = z*z; z4 = z2*z2;
    float p = fmaf(fmaf(fmaf(fmaf(C.F4, z, C.F3), z, C.F2), z, C.F1), z, 1.f);
    return fmaf(C.FLln2*z4, flg2(z), p);
}

static __device__ __forceinline__ void eval_fdf(const Coefs& C, float z, float& f, float& df)
{
    float z2, z4; f = evalf(C, z, z2, z4);
    float q = fmaf(fmaf(fmaf(fmaf(C.Q4, z, C.Q3), z, C.Q2), z, C.Q1), z, -4.f);
    df = fmaf(4.f, f, q) * frcp(z);
}

// Fused L + dL + Vc integrands at one quadrature point (shared f, bp, D).
static __device__ __forceinline__ void ldlv_point(const Coefs& C, float zs, float fs, float inv_fs,
                                                  float K12, float y, float omy2, float inv_w,
                                                  float& iL, float& idL, float& iVc)
{
    float r4 = inv_w*inv_w;
    float z = zs*omy2;
    float z2, z4; float f = evalf(C, z, z2, z4);
    float q = fmaf(fmaf(fmaf(fmaf(C.Q4, z, C.Q3), z, C.Q2), z, C.Q1), z, -4.f);
    float t4 = fmaf(4.f, f, q);                       // z*df
    float fr = f*inv_fs;
    float r4fr = r4*fr;
    float m = fmaxf(r4fr - 1.f, EPS_F);
    float rm = frsq(m);
    float bp  = fmaf(fmaf(fmaf(C.c3, z, C.c2), z, C.c1), z, 1.f);
    float dbp = fmaf(fmaf(C.d3, z, C.d2), z, C.c1);
    float Dd = (1.f - z2)*(1.f + z2);                 // 1 - z^4
    float rsq = frsq(Dd);
    float invD = rsq*rsq;
    float sg = bp*rsq;                                // sqrt(g)
    iL = sg*rm*y;
    float zdgg = fmaf(2.f*z*dbp, frcp(bp), 4.f*(z4*invD));   // z*dg/g
    float A1 = r4fr*(K12 + zdgg);
    float A2 = t4*(r4*inv_fs);                        // zs^4/z^3 * df/fs
    float brk = (A1 - A2) - (2.f + zdgg);
    idL = brk*iL*(rm*rm);                             // /2 folded into 2/pi
    // connected V piece
    float fg = fmaxf(f*(bp*bp)*invD, EPS_F);
    float sfg = fsqt(fg);
    float w2 = omy2*omy2; w2 = w2*w2;                 // w^2 = (1-y^2)^4
    float tt = fmaxf(fmaf(-w2*fs, frcp(f), 1.f), EPS_F);  // 1 - w^2*fs/f
    iVc = sfg*inv_w*(frsq(tt) - 1.f)*y;
}

// V disconnected integrand (own grid y2 on [0.001, 1.0])
static __device__ __forceinline__ float vd_point(const Coefs& C, float zs, float y2)
{
    float z = fmaf(zs - 1.f, y2, 1.f);                // 1 - (1-zs)*y2
    float z2, z4; float f = evalf(C, z, z2, z4);
    float bp = fmaf(fmaf(fmaf(C.c3, z, C.c2), z, C.c1), z, 1.f);
    float Dd = (1.f - z2)*(1.f + z2);
    float rsq = frsq(Dd);
    float invD = rsq*rsq;
    float fg = fmaxf(f*(bp*bp)*invD, EPS_F);
    float rz = frcp(z);
    return fsqt(fg)*(rz*rz);
}

// Exact tail of the disconnected trapz (last KTAIL points of the y2 grid).
static __device__ __forceinline__ float vd_tail(const Coefs& C, float zs)
{
    const float h2 = 0.999f/999.f;
    float s = 0.f;
    #pragma unroll 4
    for (int k = KSPLIT; k < NPTS; ++k) {
        float y2 = 0.001f + h2*(float)k;
        float W2 = (k == NPTS-1) ? 0.5f*h2 : h2;
        s = fmaf(W2, vd_point(C, zs, y2), s);
    }
    return s;
}

// Quadrature table: y, (1-y)(1+y), inv_w = (1-y^2)^-2, trapz weight.
static __device__ void build_tab(float4* tab)
{
    const float h = 0.998f/999.f;
    for (int k = threadIdx.x; k < NPTS; k += blockDim.x) {
        float y = 0.001f + h*(float)k;
        float omy2 = (1.f - y)*(1.f + y);
        float inv_w = 1.f/(omy2*omy2);
        float W = h;
        if      (k == 0)   W = 0.5f*h + 0.001f + 0.5f*(1.0e-6f)/h;
        else if (k == 1)   W = h - 0.5f*(1.0e-6f)/h;
        else if (k == 999) W = 0.5f*h + 0.5f*(1.f - y);
        tab[k] = make_float4(y, omy2, inv_w, W);
    }
}

// ---------------------------------------------------------------------------
// k_table: TWO warps per grid zs (halves of the 1000-pt quadrature), 4 zs per
// 256-thread block -> 4096 warps chip-wide.
// ---------------------------------------------------------------------------
__global__ void __launch_bounds__(256) k_table(const float* __restrict__ a,
                                               const float* __restrict__ b,
                                               const float* __restrict__ lc)
{
    __shared__ float4 tab[NPTS];
    __shared__ float part[8][5];
    build_tab(tab);
    __syncthreads();

    Coefs C; make_coefs(a[0], a[1], b[0], b[1], C);
    float coef = expf(lc[0]);

    int wid  = threadIdx.x >> 5;
    int lane = threadIdx.x & 31;
    int e    = wid >> 1;           // entry within block: 0..3
    int half = wid & 1;            // 0: k in [0,500), 1: k in [500,1000)
    int j = blockIdx.x*4 + e;
    float zs = ZLO + DZ*(float)j;

    float fs, dfs; eval_fdf(C, zs, fs, dfs);
    float inv_fs = frcp(fs);
    float K12 = fmaf(zs*dfs, inv_fs, 2.f);

    const float h2 = 0.999f/999.f;
    float sL = 0.f, sD = 0.f, sC = 0.f, sH = 0.f, sT = 0.f;
    int k0 = half*500, k1 = k0 + 500;
    for (int k = k0 + lane; k < k1; k += 32) {
        float4 t = tab[k];
        float iL, idL, iVc;
        ldlv_point(C, zs, fs, inv_fs, K12, t.x, t.y, t.z, iL, idL, iVc);
        sL = fmaf(t.w, iL, sL);
        sD = fmaf(t.w, idL, sD);
        sC = fmaf(t.w, iVc, sC);
        float y2 = 0.001f + h2*(float)k;
        float W2 = (k == 0) ? (0.0005f + 0.5f*h2) : ((k == 999) ? 0.5f*h2 : h2);
        float vd = W2*vd_point(C, zs, y2);
        if (k < KSPLIT) sH += vd; else sT += vd;
    }
    #pragma unroll
    for (int o = 16; o; o >>= 1) {
        sL += __shfl_xor_sync(0xffffffffu, sL, o);
        sD += __shfl_xor_sync(0xffffffffu, sD, o);
        sC += __shfl_xor_sync(0xffffffffu, sC, o);
        sH += __shfl_xor_sync(0xffffffffu, sH, o);
        sT += __shfl_xor_sync(0xffffffffu, sT, o);
    }
    if (lane == 0) {
        part[wid][0] = sL; part[wid][1] = sD; part[wid][2] = sC;
        part[wid][3] = sH; part[wid][4] = sT;
    }
    __syncthreads();
    if (half == 0 && lane == 0) {
        sL = part[wid][0] + part[wid+1][0];
        sD = part[wid][1] + part[wid+1][1];
        sC = part[wid][2] + part[wid+1][2];
        sH = part[wid][3] + part[wid+1][3];
        sT = part[wid][4] + part[wid+1][4];
        g_L[j]  = 4.f*zs*sL*INVPI_F;
        g_dL[j] = sD*(2.f*INVPI_F);
        g_sC[j] = sC;
        g_H[j]  = sH;
        float Vc = coef*PI_F*4.f*sC/zs;
        float Vd = coef*PI_F*2.f*(1.f - zs)*((sH + sT) + 0.0005f);
        g_V[j]  = Vc - Vd;
    }
}

// ---------------------------------------------------------------------------
// k_scal: one block. jmax (dL sign change), jcrit (V crossing) -> L_crit.
// ---------------------------------------------------------------------------
__global__ void __launch_bounds__(1024) k_scal()
{
    __shared__ int s_jmax, s_jcrit;
    int tid = threadIdx.x;
    if (tid == 0) { s_jmax = TABN - 1; s_jcrit = TABN; }
    __syncthreads();

    for (int j = tid; j < TABN - 1; j += 1024)
        if (g_dL[j] >= 0.f && g_dL[j+1] < 0.f) atomicMin(&s_jmax, j);
    __syncthreads();
    int jmax = s_jmax;
    if (jmax < 1) jmax = 1;

    int j001 = (int)ceilf((0.001f - ZLO)/DZ);
    for (int j = tid; j < jmax; j += 1024)
        if (j >= j001 && g_V[j] <= 0.f && g_V[j+1] > 0.f) atomicMin(&s_jcrit, j);
    __syncthreads();

    if (tid == 0) {
        int jc = (s_jcrit < TABN) ? s_jcrit : (jmax - 1);
        if (jc < 0) jc = 0;
        float V0 = g_V[jc], V1 = g_V[jc+1];
        float t = (-V0) / fmaxf(V1 - V0, 1e-30f);
        t = fminf(fmaxf(t, 0.f), 1.f);
        float L0 = g_L[jc], L1 = g_L[jc+1];
        float m0 = DZ*g_dL[jc], m1 = DZ*g_dL[jc+1];
        float d = L1 - L0;
        float c2 = 3.f*d - 2.f*m0 - m1;
        float c3 = m0 + m1 - 2.f*d;
        g_Lcrit = ((c3*t + c2)*t + m0)*t + L0;
        g_jmax = jmax;
    }
}

// Catmull-Rom interpolation on a gmem table at cell (j, t).
static __device__ __forceinline__ float cr_interp_g(const float* __restrict__ T, int j, float t)
{
    float V0 = __ldg(&T[j]), V1 = __ldg(&T[j+1]);
    float Vm = (j > 0) ? __ldg(&T[j-1]) : V0;
    float Vp = (j+2 < TABN) ? __ldg(&T[j+2]) : V1;
    float dv = V1 - V0;
    float m0 = (j > 0) ? 0.5f*(V1 - Vm) : dv;
    float m1 = (j+2 < TABN) ? 0.5f*(Vp - V0) : dv;
    float e2 = 3.f*dv - 2.f*m0 - m1;
    float e3 = m0 + m1 - 2.f*dv;
    return ((e3*t + e2)*t + m0)*t + V0;
}

// ---------------------------------------------------------------------------
// k_solve: one THREAD per element, 32-thread blocks spread chip-wide; tables
// read straight from gmem (L1/L2 resident).
// ---------------------------------------------------------------------------
__global__ void __launch_bounds__(32) k_solve(const float* __restrict__ Ls,
                                              const float* __restrict__ a,
                                              const float* __restrict__ b,
                                              const float* __restrict__ lc,
                                              float* __restrict__ out, int B)
{
    int i = blockIdx.x*32 + threadIdx.x;
    if (i >= B) return;

    Coefs C; make_coefs(a[0], a[1], b[0], b[1], C);
    float coef = expf(lc[0]);
    float L_crit = g_Lcrit;
    int jmax = g_jmax;

    float Lq = Ls[i];
    bool valid = Lq < L_crit;
    float Leff = valid ? Lq : 0.5f*L_crit;

    // binary search: largest j in [0, jmax-1] with g_L[j] <= Leff
    int lo = 0, hi = jmax;
    #pragma unroll
    for (int s = 0; s < 11; ++s) {
        int mid = (lo + hi) >> 1;
        bool c = (__ldg(&g_L[mid]) <= Leff);
        lo = c ? mid : lo;
        hi = c ? hi : mid;
    }
    int j = lo;

    // Hermite inversion inside cell j (nodes + exact derivatives)
    float L0 = __ldg(&g_L[j]), L1 = __ldg(&g_L[j+1]);
    float m0 = DZ*__ldg(&g_dL[j]), m1 = DZ*__ldg(&g_dL[j+1]);
    float d = L1 - L0;
    float c2 = 3.f*d - 2.f*m0 - m1;
    float c3 = m0 + m1 - 2.f*d;
    float t = (Leff - L0)*frcp(fmaxf(d, 1e-30f));
    t = fminf(fmaxf(t, 0.f), 1.f);
    #pragma unroll
    for (int it = 0; it < 3; ++it) {
        float H  = ((c3*t + c2)*t + m0)*t + L0 - Leff;
        float Hp = (3.f*c3*t + 2.f*c2)*t + m0;
        t = t - H*frcp(Hp);
        t = fminf(fmaxf(t, 0.f), 1.f);
    }
    float zs = ZLO + DZ*((float)j + t);
    zs = fminf(fmaxf(zs, 1e-4f), 0.9995f);

    // V: smooth parts interpolated, singular parts exact
    float sC = cr_interp_g(g_sC, j, t);
    float sH = cr_interp_g(g_H,  j, t);
    float tail = vd_tail(C, zs);
    float Vc = coef*PI_F*4.f*sC/zs;
    float Vd = coef*PI_F*2.f*(1.f - zs)*((sH + tail) + 0.0005f);
    float V = Vc - Vd;

    out[i] = valid ? V : 0.f;
}

extern "C" void kernel_launch(void* const* d_in, const int* in_sizes, int n_in,
                              void* d_out, int out_size)
{
    const float* Ls = (const float*)d_in[0];
    const float* a  = (const float*)d_in[1];
    const float* b  = (const float*)d_in[2];
    const float* lc = (const float*)d_in[3];
    float* out = (float*)d_out;
    int B = in_sizes[0];

    k_table<<<TABN/4, 256>>>(a, b, lc);
    k_scal<<<1, 1024>>>();
    int blocks = (B + 31)/32;
    if (blocks > 0)
        k_solve<<<blocks, 32>>>(Ls, a, b, lc, out, B);
}

// round 8
// speedup vs baseline: 20.2764x; 1.2764x over previous
#include <cuda_runtime.h>
#include <math.h>

#define PI_F     3.14159265358979f
#define INVPI_F  0.3183098861837907f
#define EPS_F    1e-12f
#define NPTS     1000
#define KTAIL    64                 // last KTAIL disconnected-grid terms: exact per element
#define KSPLIT   (NPTS - KTAIL)     // 936
#define TABN     1024
#define ZLO      1e-4f
#define ZHI      0.9995f
#define DZ       ((ZHI - ZLO) / (float)(TABN - 1))
#define LN2_F    0.69314718055994531f

#define ENT_PER_BLK 2               // zs entries per 256-thread block
#define WARPS_PER_ENT 4             // warps per entry (250 quadrature points each)
#define TBLOCKS  (TABN / ENT_PER_BLK)

__device__ float g_L[TABN];
__device__ float g_dL[TABN];
__device__ float g_sC[TABN];   // connected reduced integral (smooth in zs)
__device__ float g_H[TABN];    // disconnected sum, k < KSPLIT only (smooth in zs)
__device__ float g_V[TABN];    // full V at nodes (zs_crit sign crossing only)
__device__ float g_Lcrit;
__device__ int   g_jmax;
__device__ unsigned int g_ctr; // last-block-done counter (self-resetting)

struct Coefs {
    float F1, F2, F3, F4, FLln2;   // f(z) = 1 + F1 z + ... + F4 z^4 + (FLln2*z^4)*lg2(z)
    float Q1, Q2, Q3, Q4;          // q(z) = -4 + Q1 z + ...; z*df = 4f + q
    float c1, c2, c3;              // bp(z) = 1 + c1 z + c2 z^2 + c3 z^3; B = bp^2
    float d2, d3;                  // bp'(z) = c1 + d2 z + d3 z^2
};

static __device__ __forceinline__ float frcp(float x){ float r; asm("rcp.approx.f32 %0,%1;"   : "=f"(r) : "f"(x)); return r; }
static __device__ __forceinline__ float frsq(float x){ float r; asm("rsqrt.approx.f32 %0,%1;" : "=f"(r) : "f"(x)); return r; }
static __device__ __forceinline__ float fsqt(float x){ float r; asm("sqrt.approx.f32 %0,%1;"  : "=f"(r) : "f"(x)); return r; }
static __device__ __forceinline__ float flg2(float x){ float r; asm("lg2.approx.f32 %0,%1;"   : "=f"(r) : "f"(x)); return r; }

static __device__ __forceinline__ void make_coefs(float a0, float a1, float b0, float b1, Coefs& C)
{
    float w1 = 2.f*a0;
    float w2 = fmaf(a0, a0, 2.f*a1);
    float w3 = 2.f*a0*a1;
    float w4 = a1*a1;
    C.F1 = (4.f/3.f)*w1;
    C.F2 = 2.f*w2;
    C.F3 = 4.f*w3;
    C.F4 = -(1.f + C.F1 + C.F2 + C.F3);   // f(1)=0 identity
    float FL = -4.f*w4;
    C.FLln2 = FL * LN2_F;
    C.Q1 = -4.f*w1; C.Q2 = -4.f*w2; C.Q3 = -4.f*w3; C.Q4 = FL;
    C.c1 = b0; C.c2 = b1;
    C.c3 = ((a0 + a1) - b0) - b1;
    C.d2 = 2.f*C.c2; C.d3 = 3.f*C.c3;
}

static __device__ __forceinline__ float evalf(const Coefs& C, float z, float& z2, float& z4)
{
    z2 = z*z; z4 = z2*z2;
    float p = fmaf(fmaf(fmaf(fmaf(C.F4, z, C.F3), z, C.F2), z, C.F1), z, 1.f);
    return fmaf(C.FLln2*z4, flg2(z), p);
}

static __device__ __forceinline__ void eval_fdf(const Coefs& C, float z, float& f, float& df)
{
    float z2, z4; f = evalf(C, z, z2, z4);
    float q = fmaf(fmaf(fmaf(fmaf(C.Q4, z, C.Q3), z, C.Q2), z, C.Q1), z, -4.f);
    df = fmaf(4.f, f, q) * frcp(z);
}

// Fused L + dL + Vc integrands at one quadrature point (shared f, bp, D).
// MUFU: flg2, frsq(m), frcp(bp), frsq(Dd), frsq(f)  = 5.
static __device__ __forceinline__ void ldlv_point(const Coefs& C, float zs, float fs, float inv_fs,
                                                  float K12, float y, float omy2, float inv_w,
                                                  float& iL, float& idL, float& iVc)
{
    float r4 = inv_w*inv_w;
    float z = zs*omy2;
    float z2, z4; float f = evalf(C, z, z2, z4);
    float q = fmaf(fmaf(fmaf(fmaf(C.Q4, z, C.Q3), z, C.Q2), z, C.Q1), z, -4.f);
    float t4 = fmaf(4.f, f, q);                       // z*df
    float fr = f*inv_fs;
    float r4fr = r4*fr;
    float m = fmaxf(r4fr - 1.f, EPS_F);
    float rm = frsq(m);
    float bp  = fmaf(fmaf(fmaf(C.c3, z, C.c2), z, C.c1), z, 1.f);
    float dbp = fmaf(fmaf(C.d3, z, C.d2), z, C.c1);
    float Dd = (1.f - z2)*(1.f + z2);                 // 1 - z^4
    float rsq = frsq(Dd);
    float invD = rsq*rsq;
    float sg = bp*rsq;                                // sqrt(g)
    iL = sg*rm*y;
    float zdgg = fmaf(2.f*z*dbp, frcp(bp), 4.f*(z4*invD));   // z*dg/g
    float A1 = r4fr*(K12 + zdgg);
    float A2 = t4*(r4*inv_fs);                        // zs^4/z^3 * df/fs
    float brk = (A1 - A2) - (2.f + zdgg);
    idL = brk*iL*(rm*rm);                             // /2 folded into 2/pi
    // connected V piece: one frsq(f) gives sqrt(f)=f*rsqf and 1/f=rsqf^2
    float rsqf = frsq(fmaxf(f, EPS_F));
    float sfg = fabsf(bp)*rsq*(f*rsqf);               // sqrt(f*bp^2*invD)
    float w2 = omy2*omy2; w2 = w2*w2;                 // w^2 = (1-y^2)^4
    float tt = fmaxf(fmaf(-w2*fs, rsqf*rsqf, 1.f), EPS_F);  // 1 - w^2*fs/f
    iVc = sfg*inv_w*(frsq(tt) - 1.f)*y;
}

// V disconnected integrand (own grid y2 on [0.001, 1.0])
static __device__ __forceinline__ float vd_point(const Coefs& C, float zs, float y2)
{
    float z = fmaf(zs - 1.f, y2, 1.f);                // 1 - (1-zs)*y2
    float z2, z4; float f = evalf(C, z, z2, z4);
    float bp = fmaf(fmaf(fmaf(C.c3, z, C.c2), z, C.c1), z, 1.f);
    float Dd = (1.f - z2)*(1.f + z2);
    float rsq = frsq(Dd);
    float invD = rsq*rsq;
    float fg = fmaxf(f*(bp*bp)*invD, EPS_F);
    float rz = frcp(z);
    return fsqt(fg)*(rz*rz);
}

// Exact tail of the disconnected trapz (last KTAIL points of the y2 grid).
static __device__ __forceinline__ float vd_tail(const Coefs& C, float zs)
{
    const float h2 = 0.999f/999.f;
    float s = 0.f;
    #pragma unroll 4
    for (int k = KSPLIT; k < NPTS; ++k) {
        float y2 = 0.001f + h2*(float)k;
        float W2 = (k == NPTS-1) ? 0.5f*h2 : h2;
        s = fmaf(W2, vd_point(C, zs, y2), s);
    }
    return s;
}

// Quadrature table: y, (1-y)(1+y), inv_w = (1-y^2)^-2, trapz weight.
static __device__ void build_tab(float4* tab)
{
    const float h = 0.998f/999.f;
    for (int k = threadIdx.x; k < NPTS; k += blockDim.x) {
        float y = 0.001f + h*(float)k;
        float omy2 = (1.f - y)*(1.f + y);
        float inv_w = 1.f/(omy2*omy2);
        float W = h;
        if      (k == 0)   W = 0.5f*h + 0.001f + 0.5f*(1.0e-6f)/h;
        else if (k == 1)   W = h - 0.5f*(1.0e-6f)/h;
        else if (k == 999) W = 0.5f*h + 0.5f*(1.f - y);
        tab[k] = make_float4(y, omy2, inv_w, W);
    }
}

// ---------------------------------------------------------------------------
// k_table: 4 warps per grid zs (quarters of the 1000-pt quadrature), 2 zs per
// 256-thread block. The LAST block to finish also performs the scalar scan
// (jmax, jcrit -> L_crit), fusing k_scal.
// ---------------------------------------------------------------------------
__global__ void __launch_bounds__(256) k_table(const float* __restrict__ a,
                                               const float* __restrict__ b,
                                               const float* __restrict__ lc)
{
    __shared__ float4 tab[NPTS];
    __shared__ float part[8][5];
    __shared__ int s_last, s_jmax, s_jcrit;
    build_tab(tab);
    __syncthreads();

    Coefs C; make_coefs(a[0], a[1], b[0], b[1], C);
    float coef = expf(lc[0]);

    int wid  = threadIdx.x >> 5;
    int lane = threadIdx.x & 31;
    int e    = wid >> 2;              // entry within block: 0..1
    int quar = wid & 3;               // quarter of the quadrature
    int j = blockIdx.x*ENT_PER_BLK + e;
    float zs = ZLO + DZ*(float)j;

    float fs, dfs; eval_fdf(C, zs, fs, dfs);
    float inv_fs = frcp(fs);
    float K12 = fmaf(zs*dfs, inv_fs, 2.f);

    const float h2 = 0.999f/999.f;
    float sL = 0.f, sD = 0.f, sC = 0.f, sH = 0.f, sT = 0.f;
    int k0 = quar*250, k1 = k0 + 250;
    for (int k = k0 + lane; k < k1; k += 32) {
        float4 t = tab[k];
        float iL, idL, iVc;
        ldlv_point(C, zs, fs, inv_fs, K12, t.x, t.y, t.z, iL, idL, iVc);
        sL = fmaf(t.w, iL, sL);
        sD = fmaf(t.w, idL, sD);
        sC = fmaf(t.w, iVc, sC);
        float y2 = 0.001f + h2*(float)k;
        float W2 = (k == 0) ? (0.0005f + 0.5f*h2) : ((k == 999) ? 0.5f*h2 : h2);
        float vd = W2*vd_point(C, zs, y2);
        if (k < KSPLIT) sH += vd; else sT += vd;
    }
    #pragma unroll
    for (int o = 16; o; o >>= 1) {
        sL += __shfl_xor_sync(0xffffffffu, sL, o);
        sD += __shfl_xor_sync(0xffffffffu, sD, o);
        sC += __shfl_xor_sync(0xffffffffu, sC, o);
        sH += __shfl_xor_sync(0xffffffffu, sH, o);
        sT += __shfl_xor_sync(0xffffffffu, sT, o);
    }
    if (lane == 0) {
        part[wid][0] = sL; part[wid][1] = sD; part[wid][2] = sC;
        part[wid][3] = sH; part[wid][4] = sT;
    }
    __syncthreads();
    if (quar == 0 && lane == 0) {
        int w0 = e*WARPS_PER_ENT;
        sL = part[w0][0] + part[w0+1][0] + part[w0+2][0] + part[w0+3][0];
        sD = part[w0][1] + part[w0+1][1] + part[w0+2][1] + part[w0+3][1];
        sC = part[w0][2] + part[w0+1][2] + part[w0+2][2] + part[w0+3][2];
        sH = part[w0][3] + part[w0+1][3] + part[w0+2][3] + part[w0+3][3];
        sT = part[w0][4] + part[w0+1][4] + part[w0+2][4] + part[w0+3][4];
        g_L[j]  = 4.f*zs*sL*INVPI_F;
        g_dL[j] = sD*(2.f*INVPI_F);
        g_sC[j] = sC;
        g_H[j]  = sH;
        float Vc = coef*PI_F*4.f*sC/zs;
        float Vd = coef*PI_F*2.f*(1.f - zs)*((sH + sT) + 0.0005f);
        g_V[j]  = Vc - Vd;
    }
    __syncthreads();

    // last-block-done: fused scalar scan
    if (threadIdx.x == 0) {
        __threadfence();
        unsigned int done = atomicAdd(&g_ctr, 1u);
        s_last = (done == (unsigned int)(gridDim.x - 1)) ? 1 : 0;
        s_jmax = TABN - 1; s_jcrit = TABN;
    }
    __syncthreads();
    if (!s_last) return;
    __threadfence();   // ensure this block sees all other blocks' writes

    int tid = threadIdx.x;
    for (int k = tid; k < TABN - 1; k += 256)
        if (g_dL[k] >= 0.f && g_dL[k+1] < 0.f) atomicMin(&s_jmax, k);
    __syncthreads();
    int jmax = s_jmax;
    if (jmax < 1) jmax = 1;

    int j001 = (int)ceilf((0.001f - ZLO)/DZ);
    for (int k = tid; k < jmax; k += 256)
        if (k >= j001 && g_V[k] <= 0.f && g_V[k+1] > 0.f) atomicMin(&s_jcrit, k);
    __syncthreads();

    if (tid == 0) {
        int jc = (s_jcrit < TABN) ? s_jcrit : (jmax - 1);
        if (jc < 0) jc = 0;
        float V0 = g_V[jc], V1 = g_V[jc+1];
        float t = (-V0) / fmaxf(V1 - V0, 1e-30f);
        t = fminf(fmaxf(t, 0.f), 1.f);
        float L0 = g_L[jc], L1 = g_L[jc+1];
        float m0 = DZ*g_dL[jc], m1 = DZ*g_dL[jc+1];
        float d = L1 - L0;
        float c2 = 3.f*d - 2.f*m0 - m1;
        float c3 = m0 + m1 - 2.f*d;
        g_Lcrit = ((c3*t + c2)*t + m0)*t + L0;
        g_jmax = jmax;
        g_ctr = 0u;    // reset for next graph replay
    }
}

// Catmull-Rom interpolation on a gmem table at cell (j, t).
static __device__ __forceinline__ float cr_interp_g(const float* __restrict__ T, int j, float t)
{
    float V0 = __ldg(&T[j]), V1 = __ldg(&T[j+1]);
    float Vm = (j > 0) ? __ldg(&T[j-1]) : V0;
    float Vp = (j+2 < TABN) ? __ldg(&T[j+2]) : V1;
    float dv = V1 - V0;
    float m0 = (j > 0) ? 0.5f*(V1 - Vm) : dv;
    float m1 = (j+2 < TABN) ? 0.5f*(Vp - V0) : dv;
    float e2 = 3.f*dv - 2.f*m0 - m1;
    float e3 = m0 + m1 - 2.f*dv;
    return ((e3*t + e2)*t + m0)*t + V0;
}

// ---------------------------------------------------------------------------
// k_solve: one THREAD per element, 32-thread blocks spread chip-wide.
// ---------------------------------------------------------------------------
__global__ void __launch_bounds__(32) k_solve(const float* __restrict__ Ls,
                                              const float* __restrict__ a,
                                              const float* __restrict__ b,
                                              const float* __restrict__ lc,
                                              float* __restrict__ out, int B)
{
    int i = blockIdx.x*32 + threadIdx.x;
    if (i >= B) return;

    Coefs C; make_coefs(a[0], a[1], b[0], b[1], C);
    float coef = expf(lc[0]);
    float L_crit = g_Lcrit;
    int jmax = g_jmax;

    float Lq = Ls[i];
    bool valid = Lq < L_crit;
    float Leff = valid ? Lq : 0.5f*L_crit;

    // binary search: largest j in [0, jmax-1] with g_L[j] <= Leff
    int lo = 0, hi = jmax;
    #pragma unroll
    for (int s = 0; s < 10; ++s) {
        int mid = (lo + hi) >> 1;
        bool c = (__ldg(&g_L[mid]) <= Leff);
        lo = c ? mid : lo;
        hi = c ? hi : mid;
    }
    int j = lo;

    // Hermite inversion inside cell j (nodes + exact derivatives)
    float L0 = __ldg(&g_L[j]), L1 = __ldg(&g_L[j+1]);
    float m0 = DZ*__ldg(&g_dL[j]), m1 = DZ*__ldg(&g_dL[j+1]);
    float d = L1 - L0;
    float c2 = 3.f*d - 2.f*m0 - m1;
    float c3 = m0 + m1 - 2.f*d;
    float t = (Leff - L0)*frcp(fmaxf(d, 1e-30f));
    t = fminf(fmaxf(t, 0.f), 1.f);
    #pragma unroll
    for (int it = 0; it < 3; ++it) {
        float H  = ((c3*t + c2)*t + m0)*t + L0 - Leff;
        float Hp = (3.f*c3*t + 2.f*c2)*t + m0;
        t = t - H*frcp(Hp);
        t = fminf(fmaxf(t, 0.f), 1.f);
    }
    float zs = ZLO + DZ*((float)j + t);
    zs = fminf(fmaxf(zs, 1e-4f), 0.9995f);

    // V: smooth parts interpolated, singular parts exact
    float sC = cr_interp_g(g_sC, j, t);
    float sH = cr_interp_g(g_H,  j, t);
    float tail = vd_tail(C, zs);
    float Vc = coef*PI_F*4.f*sC/zs;
    float Vd = coef*PI_F*2.f*(1.f - zs)*((sH + tail) + 0.0005f);
    float V = Vc - Vd;

    out[i] = valid ? V : 0.f;
}

extern "C" void kernel_launch(void* const* d_in, const int* in_sizes, int n_in,
                              void* d_out, int out_size)
{
    const float* Ls = (const float*)d_in[0];
    const float* a  = (const float*)d_in[1];
    const float* b  = (const float*)d_in[2];
    const float* lc = (const float*)d_in[3];
    float* out = (float*)d_out;
    int B = in_sizes[0];

    k_table<<<TBLOCKS, 256>>>(a, b, lc);
    int blocks = (B + 31)/32;
    if (blocks > 0)
        k_solve<<<blocks, 32>>>(Ls, a, b, lc, out, B);
}

// round 9
// speedup vs baseline: 22.2546x; 1.0976x over previous
#include <cuda_runtime.h>
#include <math.h>

#define PI_F     3.14159265358979f
#define INVPI_F  0.3183098861837907f
#define EPS_F    1e-12f
#define NPTS     1000
#define KTAIL    64                 // last KTAIL disconnected-grid terms: exact per element
#define KSPLIT   (NPTS - KTAIL)     // 936
#define TABN     1024
#define ZLO      1e-4f
#define ZHI      0.9995f
#define DZ       ((ZHI - ZLO) / (float)(TABN - 1))
#define LN2_F    0.69314718055994531f

#define ENT_PER_BLK 2               // zs entries per 256-thread block
#define WARPS_PER_ENT 4             // warps per entry (250 quadrature points each)
#define TBLOCKS  (TABN / ENT_PER_BLK)

__device__ float g_L[TABN];
__device__ float g_dL[TABN];
__device__ float g_sC[TABN];   // connected reduced integral (smooth in zs)
__device__ float g_H[TABN];    // disconnected sum, k < KSPLIT only (smooth in zs)
__device__ float g_V[TABN];    // full V at nodes (zs_crit sign crossing only)
__device__ float g_Lcrit;
__device__ int   g_jmax;
__device__ unsigned int g_ctr; // last-block-done counter (self-resetting)

struct Coefs {
    float F1, F2, F3, F4, FLln2;   // f(z) = 1 + F1 z + ... + F4 z^4 + (FLln2*z^4)*lg2(z)
    float Q1, Q2, Q3, Q4;          // q(z) = -4 + Q1 z + ...; z*df = 4f + q
    float c1, c2, c3;              // bp(z) = 1 + c1 z + c2 z^2 + c3 z^3; B = bp^2
    float d2, d3;                  // bp'(z) = c1 + d2 z + d3 z^2
};

static __device__ __forceinline__ float frcp(float x){ float r; asm("rcp.approx.f32 %0,%1;"   : "=f"(r) : "f"(x)); return r; }
static __device__ __forceinline__ float frsq(float x){ float r; asm("rsqrt.approx.f32 %0,%1;" : "=f"(r) : "f"(x)); return r; }
static __device__ __forceinline__ float fsqt(float x){ float r; asm("sqrt.approx.f32 %0,%1;"  : "=f"(r) : "f"(x)); return r; }
static __device__ __forceinline__ float flg2(float x){ float r; asm("lg2.approx.f32 %0,%1;"   : "=f"(r) : "f"(x)); return r; }

static __device__ __forceinline__ void make_coefs(float a0, float a1, float b0, float b1, Coefs& C)
{
    float w1 = 2.f*a0;
    float w2 = fmaf(a0, a0, 2.f*a1);
    float w3 = 2.f*a0*a1;
    float w4 = a1*a1;
    C.F1 = (4.f/3.f)*w1;
    C.F2 = 2.f*w2;
    C.F3 = 4.f*w3;
    C.F4 = -(1.f + C.F1 + C.F2 + C.F3);   // f(1)=0 identity
    float FL = -4.f*w4;
    C.FLln2 = FL * LN2_F;
    C.Q1 = -4.f*w1; C.Q2 = -4.f*w2; C.Q3 = -4.f*w3; C.Q4 = FL;
    C.c1 = b0; C.c2 = b1;
    C.c3 = ((a0 + a1) - b0) - b1;
    C.d2 = 2.f*C.c2; C.d3 = 3.f*C.c3;
}

static __device__ __forceinline__ float evalf(const Coefs& C, float z, float& z2, float& z4)
{
    z2 = z*z; z4 = z2*z2;
    float p = fmaf(fmaf(fmaf(fmaf(C.F4, z, C.F3), z, C.F2), z, C.F1), z, 1.f);
    return fmaf(C.FLln2*z4, flg2(z), p);
}

static __device__ __forceinline__ void eval_fdf(const Coefs& C, float z, float& f, float& df)
{
    float z2, z4; f = evalf(C, z, z2, z4);
    float q = fmaf(fmaf(fmaf(fmaf(C.Q4, z, C.Q3), z, C.Q2), z, C.Q1), z, -4.f);
    df = fmaf(4.f, f, q) * frcp(z);
}

// Fused L + dL + Vc integrands at one quadrature point (shared f, bp, D).
static __device__ __forceinline__ void ldlv_point(const Coefs& C, float zs, float fs, float inv_fs,
                                                  float K12, float y, float omy2, float inv_w,
                                                  float& iL, float& idL, float& iVc)
{
    float r4 = inv_w*inv_w;
    float z = zs*omy2;
    float z2, z4; float f = evalf(C, z, z2, z4);
    float q = fmaf(fmaf(fmaf(fmaf(C.Q4, z, C.Q3), z, C.Q2), z, C.Q1), z, -4.f);
    float t4 = fmaf(4.f, f, q);                       // z*df
    float fr = f*inv_fs;
    float r4fr = r4*fr;
    float m = fmaxf(r4fr - 1.f, EPS_F);
    float rm = frsq(m);
    float bp  = fmaf(fmaf(fmaf(C.c3, z, C.c2), z, C.c1), z, 1.f);
    float dbp = fmaf(fmaf(C.d3, z, C.d2), z, C.c1);
    float Dd = (1.f - z2)*(1.f + z2);                 // 1 - z^4
    float rsq = frsq(Dd);
    float invD = rsq*rsq;
    float sg = bp*rsq;                                // sqrt(g)
    iL = sg*rm*y;
    float zdgg = fmaf(2.f*z*dbp, frcp(bp), 4.f*(z4*invD));   // z*dg/g
    float A1 = r4fr*(K12 + zdgg);
    float A2 = t4*(r4*inv_fs);                        // zs^4/z^3 * df/fs
    float brk = (A1 - A2) - (2.f + zdgg);
    idL = brk*iL*(rm*rm);                             // /2 folded into 2/pi
    // connected V piece: one frsq(f) gives sqrt(f)=f*rsqf and 1/f=rsqf^2
    float rsqf = frsq(fmaxf(f, EPS_F));
    float sfg = fabsf(bp)*rsq*(f*rsqf);               // sqrt(f*bp^2*invD)
    float w2 = omy2*omy2; w2 = w2*w2;                 // w^2 = (1-y^2)^4
    float tt = fmaxf(fmaf(-w2*fs, rsqf*rsqf, 1.f), EPS_F);  // 1 - w^2*fs/f
    iVc = sfg*inv_w*(frsq(tt) - 1.f)*y;
}

// V disconnected integrand (own grid y2 on [0.001, 1.0])
static __device__ __forceinline__ float vd_point(const Coefs& C, float zs, float y2)
{
    float z = fmaf(zs - 1.f, y2, 1.f);                // 1 - (1-zs)*y2
    float z2, z4; float f = evalf(C, z, z2, z4);
    float bp = fmaf(fmaf(fmaf(C.c3, z, C.c2), z, C.c1), z, 1.f);
    float Dd = (1.f - z2)*(1.f + z2);
    float rsq = frsq(Dd);
    float invD = rsq*rsq;
    float fg = fmaxf(f*(bp*bp)*invD, EPS_F);
    float rz = frcp(z);
    return fsqt(fg)*(rz*rz);
}

// Quadrature table: y, (1-y)(1+y), inv_w = (1-y^2)^-2, trapz weight.
static __device__ void build_tab(float4* tab)
{
    const float h = 0.998f/999.f;
    for (int k = threadIdx.x; k < NPTS; k += blockDim.x) {
        float y = 0.001f + h*(float)k;
        float omy2 = (1.f - y)*(1.f + y);
        float inv_w = 1.f/(omy2*omy2);
        float W = h;
        if      (k == 0)   W = 0.5f*h + 0.001f + 0.5f*(1.0e-6f)/h;
        else if (k == 1)   W = h - 0.5f*(1.0e-6f)/h;
        else if (k == 999) W = 0.5f*h + 0.5f*(1.f - y);
        tab[k] = make_float4(y, omy2, inv_w, W);
    }
}

// ---------------------------------------------------------------------------
// k_table: 4 warps per grid zs, 2 zs per 256-thread block; the LAST block
// also performs the scalar scan (jmax, jcrit -> L_crit).
// ---------------------------------------------------------------------------
__global__ void __launch_bounds__(256) k_table(const float* __restrict__ a,
                                               const float* __restrict__ b,
                                               const float* __restrict__ lc)
{
    __shared__ float4 tab[NPTS];
    __shared__ float part[8][5];
    __shared__ int s_last, s_jmax, s_jcrit;
    build_tab(tab);
    __syncthreads();

    Coefs C; make_coefs(a[0], a[1], b[0], b[1], C);
    float coef = expf(lc[0]);

    int wid  = threadIdx.x >> 5;
    int lane = threadIdx.x & 31;
    int e    = wid >> 2;              // entry within block: 0..1
    int quar = wid & 3;               // quarter of the quadrature
    int j = blockIdx.x*ENT_PER_BLK + e;
    float zs = ZLO + DZ*(float)j;

    float fs, dfs; eval_fdf(C, zs, fs, dfs);
    float inv_fs = frcp(fs);
    float K12 = fmaf(zs*dfs, inv_fs, 2.f);

    const float h2 = 0.999f/999.f;
    float sL = 0.f, sD = 0.f, sC = 0.f, sH = 0.f, sT = 0.f;
    int k0 = quar*250, k1 = k0 + 250;
    for (int k = k0 + lane; k < k1; k += 32) {
        float4 t = tab[k];
        float iL, idL, iVc;
        ldlv_point(C, zs, fs, inv_fs, K12, t.x, t.y, t.z, iL, idL, iVc);
        sL = fmaf(t.w, iL, sL);
        sD = fmaf(t.w, idL, sD);
        sC = fmaf(t.w, iVc, sC);
        float y2 = 0.001f + h2*(float)k;
        float W2 = (k == 0) ? (0.0005f + 0.5f*h2) : ((k == 999) ? 0.5f*h2 : h2);
        float vd = W2*vd_point(C, zs, y2);
        if (k < KSPLIT) sH += vd; else sT += vd;
    }
    #pragma unroll
    for (int o = 16; o; o >>= 1) {
        sL += __shfl_xor_sync(0xffffffffu, sL, o);
        sD += __shfl_xor_sync(0xffffffffu, sD, o);
        sC += __shfl_xor_sync(0xffffffffu, sC, o);
        sH += __shfl_xor_sync(0xffffffffu, sH, o);
        sT += __shfl_xor_sync(0xffffffffu, sT, o);
    }
    if (lane == 0) {
        part[wid][0] = sL; part[wid][1] = sD; part[wid][2] = sC;
        part[wid][3] = sH; part[wid][4] = sT;
    }
    __syncthreads();
    if (quar == 0 && lane == 0) {
        int w0 = e*WARPS_PER_ENT;
        sL = part[w0][0] + part[w0+1][0] + part[w0+2][0] + part[w0+3][0];
        sD = part[w0][1] + part[w0+1][1] + part[w0+2][1] + part[w0+3][1];
        sC = part[w0][2] + part[w0+1][2] + part[w0+2][2] + part[w0+3][2];
        sH = part[w0][3] + part[w0+1][3] + part[w0+2][3] + part[w0+3][3];
        sT = part[w0][4] + part[w0+1][4] + part[w0+2][4] + part[w0+3][4];
        g_L[j]  = 4.f*zs*sL*INVPI_F;
        g_dL[j] = sD*(2.f*INVPI_F);
        g_sC[j] = sC;
        g_H[j]  = sH;
        float Vc = coef*PI_F*4.f*sC/zs;
        float Vd = coef*PI_F*2.f*(1.f - zs)*((sH + sT) + 0.0005f);
        g_V[j]  = Vc - Vd;
    }
    __syncthreads();

    // last-block-done: fused scalar scan
    if (threadIdx.x == 0) {
        __threadfence();
        unsigned int done = atomicAdd(&g_ctr, 1u);
        s_last = (done == (unsigned int)(gridDim.x - 1)) ? 1 : 0;
        s_jmax = TABN - 1; s_jcrit = TABN;
    }
    __syncthreads();
    if (!s_last) return;
    __threadfence();

    int tid = threadIdx.x;
    for (int k = tid; k < TABN - 1; k += 256)
        if (g_dL[k] >= 0.f && g_dL[k+1] < 0.f) atomicMin(&s_jmax, k);
    __syncthreads();
    int jmax = s_jmax;
    if (jmax < 1) jmax = 1;

    int j001 = (int)ceilf((0.001f - ZLO)/DZ);
    for (int k = tid; k < jmax; k += 256)
        if (k >= j001 && g_V[k] <= 0.f && g_V[k+1] > 0.f) atomicMin(&s_jcrit, k);
    __syncthreads();

    if (tid == 0) {
        int jc = (s_jcrit < TABN) ? s_jcrit : (jmax - 1);
        if (jc < 0) jc = 0;
        float V0 = g_V[jc], V1 = g_V[jc+1];
        float t = (-V0) / fmaxf(V1 - V0, 1e-30f);
        t = fminf(fmaxf(t, 0.f), 1.f);
        float L0 = g_L[jc], L1 = g_L[jc+1];
        float m0 = DZ*g_dL[jc], m1 = DZ*g_dL[jc+1];
        float d = L1 - L0;
        float c2 = 3.f*d - 2.f*m0 - m1;
        float c3 = m0 + m1 - 2.f*d;
        g_Lcrit = ((c3*t + c2)*t + m0)*t + L0;
        g_jmax = jmax;
        g_ctr = 0u;    // reset for next graph replay
    }
}

// Catmull-Rom interpolation on a gmem table at cell (j, t).
static __device__ __forceinline__ float cr_interp_g(const float* __restrict__ T, int j, float t)
{
    float V0 = __ldg(&T[j]), V1 = __ldg(&T[j+1]);
    float Vm = (j > 0) ? __ldg(&T[j-1]) : V0;
    float Vp = (j+2 < TABN) ? __ldg(&T[j+2]) : V1;
    float dv = V1 - V0;
    float m0 = (j > 0) ? 0.5f*(V1 - Vm) : dv;
    float m1 = (j+2 < TABN) ? 0.5f*(Vp - V0) : dv;
    float e2 = 3.f*dv - 2.f*m0 - m1;
    float e3 = m0 + m1 - 2.f*dv;
    return ((e3*t + e2)*t + m0)*t + V0;
}

// ---------------------------------------------------------------------------
// k_solve: EIGHT lanes per element (32k threads, 1024 warps). Lanes 8g..8g+7
// handle element g of the warp: the search/inversion/interp are computed
// redundantly (broadcast loads); the 64-term vd tail is split 8 ways and
// reduced with 3 shfl steps.
// ---------------------------------------------------------------------------
__global__ void __launch_bounds__(256) k_solve(const float* __restrict__ Ls,
                                               const float* __restrict__ a,
                                               const float* __restrict__ b,
                                               const float* __restrict__ lc,
                                               float* __restrict__ out, int B)
{
    int lane = threadIdx.x & 31;
    int sub  = lane >> 3;             // element slot within warp: 0..3
    int r    = lane & 7;              // lane within 8-lane group
    int warp_g = (blockIdx.x*256 + threadIdx.x) >> 5;
    int i = warp_g*4 + sub;           // element index
    if (i >= B) return;

    Coefs C; make_coefs(a[0], a[1], b[0], b[1], C);
    float coef = expf(lc[0]);
    float L_crit = g_Lcrit;
    int jmax = g_jmax;

    float Lq = __ldg(&Ls[i]);
    bool valid = Lq < L_crit;
    float Leff = valid ? Lq : 0.5f*L_crit;

    // binary search (redundant across the 8 lanes; loads broadcast)
    int lo = 0, hi = jmax;
    #pragma unroll
    for (int s = 0; s < 10; ++s) {
        int mid = (lo + hi) >> 1;
        bool c = (__ldg(&g_L[mid]) <= Leff);
        lo = c ? mid : lo;
        hi = c ? hi : mid;
    }
    int j = lo;

    // Hermite inversion inside cell j (nodes + exact derivatives)
    float L0 = __ldg(&g_L[j]), L1 = __ldg(&g_L[j+1]);
    float m0 = DZ*__ldg(&g_dL[j]), m1 = DZ*__ldg(&g_dL[j+1]);
    float d = L1 - L0;
    float c2 = 3.f*d - 2.f*m0 - m1;
    float c3 = m0 + m1 - 2.f*d;
    float t = (Leff - L0)*frcp(fmaxf(d, 1e-30f));
    t = fminf(fmaxf(t, 0.f), 1.f);
    #pragma unroll
    for (int it = 0; it < 3; ++it) {
        float H  = ((c3*t + c2)*t + m0)*t + L0 - Leff;
        float Hp = (3.f*c3*t + 2.f*c2)*t + m0;
        t = t - H*frcp(Hp);
        t = fminf(fmaxf(t, 0.f), 1.f);
    }
    float zs = ZLO + DZ*((float)j + t);
    zs = fminf(fmaxf(zs, 1e-4f), 0.9995f);

    // split tail: lane r handles k = KSPLIT + r, r+8, ... (8 terms)
    const float h2 = 0.999f/999.f;
    float tail = 0.f;
    #pragma unroll
    for (int m = 0; m < KTAIL/8; ++m) {
        int k = KSPLIT + r + m*8;
        float y2 = 0.001f + h2*(float)k;
        float W2 = (k == NPTS-1) ? 0.5f*h2 : h2;
        tail = fmaf(W2, vd_point(C, zs, y2), tail);
    }
    #pragma unroll
    for (int o = 4; o; o >>= 1) tail += __shfl_xor_sync(0xffffffffu, tail, o);

    // smooth parts interpolated (redundant across lanes)
    float sC = cr_interp_g(g_sC, j, t);
    float sH = cr_interp_g(g_H,  j, t);
    float Vc = coef*PI_F*4.f*sC/zs;
    float Vd = coef*PI_F*2.f*(1.f - zs)*((sH + tail) + 0.0005f);
    float V = Vc - Vd;

    if (r == 0) out[i] = valid ? V : 0.f;
}

extern "C" void kernel_launch(void* const* d_in, const int* in_sizes, int n_in,
                              void* d_out, int out_size)
{
    const float* Ls = (const float*)d_in[0];
    const float* a  = (const float*)d_in[1];
    const float* b  = (const float*)d_in[2];
    const float* lc = (const float*)d_in[3];
    float* out = (float*)d_out;
    int B = in_sizes[0];

    k_table<<<TBLOCKS, 256>>>(a, b, lc);
    int elems_per_blk = 32;                 // 8 warps * 4 elements
    int blocks = (B + elems_per_blk - 1)/elems_per_blk;
    if (blocks > 0)
        k_solve<<<blocks, 256>>>(Ls, a, b, lc, out, B);
}